// round 6
// baseline (speedup 1.0000x reference)
#include <cuda_runtime.h>
#include <cuda_bf16.h>
#include <math_constants.h>
#include <cstdint>

#define MAXN 50000
#define MAXE 500000
#define C    128
#define RELS 3

// ---------------- scratch (static device memory; no allocation) ----------------
__device__ __align__(16) float g_xw[(size_t)RELS * MAXN * C];
__device__ __align__(16) float g_h[(size_t)MAXN * C];
__device__ float g_alpha[MAXE];
__device__ float g_sq[RELS * MAXN];
__device__ float g_sk[RELS * MAXN];
__device__ __align__(16) float g_wq[RELS * C];
__device__ __align__(16) float g_wk[RELS * C];
__device__ float g_cattr;
__device__ __align__(16) __nv_bfloat16 g_wt_hi[RELS * C * C];  // W^T split hi [r][n][k]
__device__ __align__(16) __nv_bfloat16 g_wt_lo[RELS * C * C];  // W^T split lo [r][n][k]
__device__ int   g_deg[MAXN];
__device__ int   g_incl[MAXN];
__device__ int   g_indptr[MAXN + 1];
__device__ int   g_cursor[MAXN];
__device__ int   g_eidx[MAXE];
__device__ int   g_bsum[64];

__device__ __forceinline__ uint32_t smem_u32(const void* p) {
    uint32_t a;
    asm("{ .reg .u64 t; cvta.to.shared.u64 t, %1; cvt.u32.u64 %0, t; }" : "=r"(a) : "l"(p));
    return a;
}
__device__ __forceinline__ void mma_bf16(float* c, const uint32_t* a, const uint32_t* b) {
    asm volatile(
        "mma.sync.aligned.m16n8k16.row.col.f32.bf16.bf16.f32 "
        "{%0,%1,%2,%3}, {%4,%5,%6,%7}, {%8,%9}, {%0,%1,%2,%3};"
        : "+f"(c[0]), "+f"(c[1]), "+f"(c[2]), "+f"(c[3])
        : "r"(a[0]), "r"(a[1]), "r"(a[2]), "r"(a[3]), "r"(b[0]), "r"(b[1]));
}
__device__ __forceinline__ void ldsm_x4(uint32_t* r, uint32_t addr) {
    asm volatile("ldmatrix.sync.aligned.m8n8.x4.shared.b16 {%0,%1,%2,%3}, [%4];"
                 : "=r"(r[0]), "=r"(r[1]), "=r"(r[2]), "=r"(r[3]) : "r"(addr));
}

// ---------------- CSR build ----------------
__global__ void k_zero_deg(int n) {
    int i = blockIdx.x * blockDim.x + threadIdx.x;
    if (i < n) g_deg[i] = 0;
}
__global__ void k_count(const int* __restrict__ dst, int e_cnt) {
    int e = blockIdx.x * blockDim.x + threadIdx.x;
    if (e < e_cnt) atomicAdd(&g_deg[dst[e]], 1);
}
__global__ void k_scanA(int n) {
    __shared__ int sh[2][1024];
    int tid = threadIdx.x;
    int i = blockIdx.x * 1024 + tid;
    int v = (i < n) ? g_deg[i] : 0;
    sh[0][tid] = v;
    __syncthreads();
    int pb = 0;
#pragma unroll
    for (int off = 1; off < 1024; off <<= 1) {
        int nb = pb ^ 1;
        int val = sh[pb][tid];
        if (tid >= off) val += sh[pb][tid - off];
        sh[nb][tid] = val;
        pb = nb;
        __syncthreads();
    }
    int incl = sh[pb][tid];
    if (i < n) g_incl[i] = incl;
    if (tid == 1023) g_bsum[blockIdx.x] = incl;
}
__global__ void k_scanB(int nblk) {
    __shared__ int sh[64];
    int t = threadIdx.x;
    int v = (t < nblk) ? g_bsum[t] : 0;
    sh[t] = v;
    __syncthreads();
#pragma unroll
    for (int off = 1; off < 64; off <<= 1) {
        int add = (t >= off) ? sh[t - off] : 0;
        __syncthreads();
        sh[t] += add;
        __syncthreads();
    }
    if (t < nblk) g_bsum[t] = sh[t] - v;
}
__global__ void k_scanC(int n) {
    int i = blockIdx.x * blockDim.x + threadIdx.x;
    if (i < n) {
        int total = g_incl[i] + g_bsum[i >> 10];
        g_indptr[i + 1] = total;
        g_cursor[i] = total - g_deg[i];
        if (i == 0) g_indptr[0] = 0;
    }
}
__global__ void k_fill(const int* __restrict__ dst, int e_cnt) {
    int e = blockIdx.x * blockDim.x + threadIdx.x;
    if (e < e_cnt) {
        int pos = atomicAdd(&g_cursor[dst[e]], 1);
        g_eidx[pos] = e;
    }
}

// ---------------- per-layer precompute ----------------
__global__ void k_prep(const float* __restrict__ w, const float* __restrict__ q,
                       const float* __restrict__ kk, const float* __restrict__ le,
                       const float* __restrict__ ee) {
    int gw = (blockIdx.x * blockDim.x + threadIdx.x) >> 5;
    int lane = threadIdx.x & 31;
    if (gw < RELS * C) {
        const float4* row = (const float4*)(w + (size_t)gw * C);
        float4 wv = row[lane];
        float4 qv = ((const float4*)q)[lane];
        float4 kv = ((const float4*)kk)[lane];
        float aq = wv.x * qv.x + wv.y * qv.y + wv.z * qv.z + wv.w * qv.w;
        float ak = wv.x * kv.x + wv.y * kv.y + wv.z * kv.z + wv.w * kv.w;
#pragma unroll
        for (int off = 16; off; off >>= 1) {
            aq += __shfl_xor_sync(0xffffffffu, aq, off);
            ak += __shfl_xor_sync(0xffffffffu, ak, off);
        }
        if (lane == 0) { g_wq[gw] = aq; g_wk[gw] = ak; }
    } else if (gw == RELS * C) {
        float p = 0.f;
        for (int o = lane; o < C; o += 32) p += le[o] * ee[o];
#pragma unroll
        for (int off = 16; off; off >>= 1) p += __shfl_xor_sync(0xffffffffu, p, off);
        if (lane == 0) g_cattr = p;
    }
}

// transpose + bf16-split W: g_wt_*[r][n][k] from W[r][k][n]
__global__ void k_prepw(const float* __restrict__ W) {
    int r = blockIdx.x;
    const float* Wr = W + (size_t)r * C * C;
    for (int idx = threadIdx.x; idx < C * C; idx += blockDim.x) {
        int k = idx >> 7, nn = idx & 127;
        float v = Wr[idx];
        __nv_bfloat16 h = __float2bfloat16(v);
        float lo = v - __bfloat162float(h);
        g_wt_hi[(size_t)r * C * C + nn * C + k] = h;
        g_wt_lo[(size_t)r * C * C + nn * C + k] = __float2bfloat16(lo);
    }
}

// ---------------- per-node attention scalars ----------------
__global__ void k_sqk(const float* __restrict__ x, int n) {
    int gw = (blockIdx.x * blockDim.x + threadIdx.x) >> 5;
    int lane = threadIdx.x & 31;
    if (gw >= n) return;
    float4 xv = ((const float4*)x)[(size_t)gw * 32 + lane];
    float aq[RELS], ak[RELS];
#pragma unroll
    for (int r = 0; r < RELS; ++r) {
        float4 wqv = ((const float4*)g_wq)[r * 32 + lane];
        float4 wkv = ((const float4*)g_wk)[r * 32 + lane];
        aq[r] = xv.x * wqv.x + xv.y * wqv.y + xv.z * wqv.z + xv.w * wqv.w;
        ak[r] = xv.x * wkv.x + xv.y * wkv.y + xv.z * wkv.z + xv.w * wkv.w;
    }
#pragma unroll
    for (int off = 16; off; off >>= 1) {
#pragma unroll
        for (int r = 0; r < RELS; ++r) {
            aq[r] += __shfl_xor_sync(0xffffffffu, aq[r], off);
            ak[r] += __shfl_xor_sync(0xffffffffu, ak[r], off);
        }
    }
    if (lane == 0) {
#pragma unroll
        for (int r = 0; r < RELS; ++r) {
            g_sq[r * n + gw] = aq[r];
            g_sk[r * n + gw] = ak[r];
        }
    }
}

// ---------------- HMMA bf16 3-term GEMM with ldmatrix: g_xw[r] = X @ W[r] ----------------
// CTA: 256 thr (8 warps), tile M=128 x N=128, K chunked 64. 3 CTAs/SM.
#define APADB 72   // stride 144B -> conflict-free ldmatrix (16B-group = (row*9+c)%8)
#define GEMM_SMEM (4 * 128 * APADB * 2)

__global__ __launch_bounds__(256, 3) void k_gemm_bf(const float* __restrict__ X, int n) {
    extern __shared__ __nv_bfloat16 smb[];
    __nv_bfloat16* Ah = smb;
    __nv_bfloat16* Al = Ah + 128 * APADB;
    __nv_bfloat16* Bh = Al + 128 * APADB;
    __nv_bfloat16* Bl = Bh + 128 * APADB;

    int r = blockIdx.y;
    int m0 = blockIdx.x * 128;
    float* Cr = g_xw + ((size_t)r * n) * C;
    const __nv_bfloat16* WTh = g_wt_hi + (size_t)r * C * C;
    const __nv_bfloat16* WTl = g_wt_lo + (size_t)r * C * C;

    int tid = threadIdx.x;
    int lane = tid & 31;
    int wid = tid >> 5;
    int wm = wid & 1;       // 64-row half
    int wn = wid >> 1;      // 32-col quarter

    uint32_t aAh = smem_u32(Ah), aAl = smem_u32(Al);
    uint32_t aBh = smem_u32(Bh), aBl = smem_u32(Bl);

    // ldmatrix lane address components (row/k within a 16x16 frag group)
    int lrow = (lane & 7) + ((lane >> 3) & 1) * 8;
    int lkoff = (lane >> 4) * 8;
    uint32_t baseA = (uint32_t)((wm * 64 + lrow) * APADB + lkoff) * 2;
    uint32_t baseB = (uint32_t)((wn * 32 + lrow) * APADB + lkoff) * 2;

    float acc[4][4][4];
#pragma unroll
    for (int a = 0; a < 4; ++a)
#pragma unroll
        for (int b = 0; b < 4; ++b)
#pragma unroll
            for (int cc = 0; cc < 4; ++cc) acc[a][b][cc] = 0.f;

    for (int kc = 0; kc < C; kc += 64) {
        // ---- load + split A: 128 rows x 64 k fp32 -> bf16 hi/lo ----
        {
            int k4 = (tid & 15) * 4;
            int rb = tid >> 4;
#pragma unroll
            for (int it = 0; it < 8; ++it) {
                int row = rb + it * 16;
                float4 v = make_float4(0.f, 0.f, 0.f, 0.f);
                if (m0 + row < n)
                    v = *(const float4*)(X + (size_t)(m0 + row) * C + kc + k4);
                __nv_bfloat16 hx = __float2bfloat16(v.x), hy = __float2bfloat16(v.y);
                __nv_bfloat16 hz = __float2bfloat16(v.z), hw = __float2bfloat16(v.w);
                __nv_bfloat162 h01 = __nv_bfloat162(hx, hy);
                __nv_bfloat162 h23 = __nv_bfloat162(hz, hw);
                __nv_bfloat162 l01 = __nv_bfloat162(__float2bfloat16(v.x - __bfloat162float(hx)),
                                                    __float2bfloat16(v.y - __bfloat162float(hy)));
                __nv_bfloat162 l23 = __nv_bfloat162(__float2bfloat16(v.z - __bfloat162float(hz)),
                                                    __float2bfloat16(v.w - __bfloat162float(hw)));
                *(__nv_bfloat162*)(Ah + row * APADB + k4)     = h01;
                *(__nv_bfloat162*)(Ah + row * APADB + k4 + 2) = h23;
                *(__nv_bfloat162*)(Al + row * APADB + k4)     = l01;
                *(__nv_bfloat162*)(Al + row * APADB + k4 + 2) = l23;
            }
        }
        // ---- load B (pre-split bf16, [n][k]) ----
        {
            int k4 = (tid & 15) * 4;
            int nb = tid >> 4;
#pragma unroll
            for (int it = 0; it < 8; ++it) {
                int nn = nb + it * 16;
                uint2 vh = *(const uint2*)(WTh + (size_t)nn * C + kc + k4);
                uint2 vl = *(const uint2*)(WTl + (size_t)nn * C + kc + k4);
                *(uint2*)(Bh + nn * APADB + k4) = vh;
                *(uint2*)(Bl + nn * APADB + k4) = vl;
            }
        }
        __syncthreads();

#pragma unroll
        for (int ks = 0; ks < 4; ++ks) {
            uint32_t koff = (uint32_t)(ks * 16) * 2;
            uint32_t ah[4][4], al[4][4], bh[4][2], bl[4][2];
#pragma unroll
            for (int mt = 0; mt < 4; ++mt) {
                ldsm_x4(ah[mt], aAh + baseA + koff + (uint32_t)(mt * 16 * APADB * 2));
                ldsm_x4(al[mt], aAl + baseA + koff + (uint32_t)(mt * 16 * APADB * 2));
            }
#pragma unroll
            for (int p = 0; p < 2; ++p) {
                uint32_t t4[4];
                ldsm_x4(t4, aBh + baseB + koff + (uint32_t)(p * 16 * APADB * 2));
                bh[2 * p][0] = t4[0]; bh[2 * p + 1][0] = t4[1];
                bh[2 * p][1] = t4[2]; bh[2 * p + 1][1] = t4[3];
                ldsm_x4(t4, aBl + baseB + koff + (uint32_t)(p * 16 * APADB * 2));
                bl[2 * p][0] = t4[0]; bl[2 * p + 1][0] = t4[1];
                bl[2 * p][1] = t4[2]; bl[2 * p + 1][1] = t4[3];
            }
            // term-outer: 16 independent accumulators between dependent writes
#pragma unroll
            for (int mt = 0; mt < 4; ++mt)
#pragma unroll
                for (int nt = 0; nt < 4; ++nt) mma_bf16(acc[mt][nt], ah[mt], bh[nt]);
#pragma unroll
            for (int mt = 0; mt < 4; ++mt)
#pragma unroll
                for (int nt = 0; nt < 4; ++nt) mma_bf16(acc[mt][nt], ah[mt], bl[nt]);
#pragma unroll
            for (int mt = 0; mt < 4; ++mt)
#pragma unroll
                for (int nt = 0; nt < 4; ++nt) mma_bf16(acc[mt][nt], al[mt], bh[nt]);
        }
        __syncthreads();
    }

    // ---- epilogue ----
#pragma unroll
    for (int mt = 0; mt < 4; ++mt) {
        int row0 = m0 + wm * 64 + mt * 16 + (lane >> 2);
        int row1 = row0 + 8;
#pragma unroll
        for (int nt = 0; nt < 4; ++nt) {
            int col = wn * 32 + nt * 8 + 2 * (lane & 3);
            if (row0 < n)
                *(float2*)(Cr + (size_t)row0 * C + col) = make_float2(acc[mt][nt][0], acc[mt][nt][1]);
            if (row1 < n)
                *(float2*)(Cr + (size_t)row1 * C + col) = make_float2(acc[mt][nt][2], acc[mt][nt][3]);
        }
    }
}

// ---------------- per-edge attention logits ----------------
__global__ void k_alpha(const int* __restrict__ src, const int* __restrict__ dst,
                        const int* __restrict__ etype, const float* __restrict__ attr,
                        int n, int e_cnt) {
    int e = blockIdx.x * blockDim.x + threadIdx.x;
    if (e >= e_cnt) return;
    int r = etype[e];
    float a = g_sq[r * n + dst[e]] + g_sk[r * n + src[e]] + g_cattr * attr[e];
    g_alpha[e] = (a > 0.f) ? a : 0.2f * a;
}

// ---------------- per-node softmax + weighted aggregation (warp per node) ----------------
__global__ void k_agg(const int* __restrict__ src, const int* __restrict__ etype,
                      const float* __restrict__ bias, float* __restrict__ out,
                      int relu, int n) {
    int gw = (blockIdx.x * blockDim.x + threadIdx.x) >> 5;
    int lane = threadIdx.x & 31;
    if (gw >= n) return;
    int beg = g_indptr[gw], end = g_indptr[gw + 1];

    float m = -CUDART_INF_F;
    for (int j = beg + lane; j < end; j += 32) m = fmaxf(m, g_alpha[g_eidx[j]]);
#pragma unroll
    for (int off = 16; off; off >>= 1) m = fmaxf(m, __shfl_xor_sync(0xffffffffu, m, off));

    float s = 0.f;
    for (int j = beg + lane; j < end; j += 32) s += __expf(g_alpha[g_eidx[j]] - m);
#pragma unroll
    for (int off = 16; off; off >>= 1) s += __shfl_xor_sync(0xffffffffu, s, off);
    float inv = 1.f / (s + 1e-16f);

    float4 acc = make_float4(0.f, 0.f, 0.f, 0.f);
    for (int j = beg; j < end; ++j) {
        int e = g_eidx[j];
        float coeff = __expf(g_alpha[e] - m) * inv;
        int sv = src[e];
        int r = etype[e];
        const float4* row = (const float4*)(g_xw + ((size_t)r * n + sv) * C);
        float4 v = row[lane];
        acc.x = fmaf(coeff, v.x, acc.x);
        acc.y = fmaf(coeff, v.y, acc.y);
        acc.z = fmaf(coeff, v.z, acc.z);
        acc.w = fmaf(coeff, v.w, acc.w);
    }
    float4 bb = ((const float4*)bias)[lane];
    acc.x += bb.x; acc.y += bb.y; acc.z += bb.z; acc.w += bb.w;
    if (relu) {
        acc.x = fmaxf(acc.x, 0.f); acc.y = fmaxf(acc.y, 0.f);
        acc.z = fmaxf(acc.z, 0.f); acc.w = fmaxf(acc.w, 0.f);
    }
    ((float4*)(out + (size_t)gw * C))[lane] = acc;
}

// ---------------- driver ----------------
extern "C" void kernel_launch(void* const* d_in, const int* in_sizes, int n_in,
                              void* d_out, int out_size) {
    const float* x    = (const float*)d_in[0];
    const int*   ei   = (const int*)d_in[1];
    const int*   et   = (const int*)d_in[2];
    const float* attr = (const float*)d_in[3];
    const float *w1 = (const float*)d_in[4],  *q1 = (const float*)d_in[5],
                *k1 = (const float*)d_in[6],  *le1 = (const float*)d_in[7],
                *e1 = (const float*)d_in[8],  *b1 = (const float*)d_in[9];
    const float *w2 = (const float*)d_in[10], *q2 = (const float*)d_in[11],
                *k2 = (const float*)d_in[12], *le2 = (const float*)d_in[13],
                *e2 = (const float*)d_in[14], *b2 = (const float*)d_in[15];

    int n = in_sizes[0] / C;
    int e_cnt = in_sizes[2];
    const int* src = ei;
    const int* dst = ei + e_cnt;

    float* h = nullptr;
    cudaGetSymbolAddress((void**)&h, g_h);

    static bool attr_set = false;
    if (!attr_set) {
        cudaFuncSetAttribute(k_gemm_bf, cudaFuncAttributeMaxDynamicSharedMemorySize, GEMM_SMEM);
        attr_set = true;
    }

    dim3 gg((n + 127) / 128, RELS);
    int nblk = (n + 1023) / 1024;
    int prep_blocks = (RELS * C + 1 + 7) / 8;

    // launch #4 = k_gemm_bf (profiled slot)
    k_prepw<<<RELS, 256>>>(w1);
    k_zero_deg<<<(n + 255) / 256, 256>>>(n);
    k_count<<<(e_cnt + 255) / 256, 256>>>(dst, e_cnt);
    k_gemm_bf<<<gg, 256, GEMM_SMEM>>>(x, n);
    k_scanA<<<nblk, 1024>>>(n);
    k_scanB<<<1, 64>>>(nblk);
    k_scanC<<<(n + 255) / 256, 256>>>(n);
    k_fill<<<(e_cnt + 255) / 256, 256>>>(dst, e_cnt);

    // layer 1 attention + aggregation
    k_prep<<<prep_blocks, 256>>>(w1, q1, k1, le1, e1);
    k_sqk<<<(n + 7) / 8, 256>>>(x, n);
    k_alpha<<<(e_cnt + 255) / 256, 256>>>(src, dst, et, attr, n, e_cnt);
    k_agg<<<(n + 7) / 8, 256>>>(src, et, b1, h, 1, n);

    // layer 2
    k_prepw<<<RELS, 256>>>(w2);
    k_gemm_bf<<<gg, 256, GEMM_SMEM>>>(h, n);
    k_prep<<<prep_blocks, 256>>>(w2, q2, k2, le2, e2);
    k_sqk<<<(n + 7) / 8, 256>>>(h, n);
    k_alpha<<<(e_cnt + 255) / 256, 256>>>(src, dst, et, attr, n, e_cnt);
    k_agg<<<(n + 7) / 8, 256>>>(src, et, b2, (float*)d_out, 0, n);
}

// round 7
// speedup vs baseline: 1.3741x; 1.3741x over previous
#include <cuda_runtime.h>
#include <cuda_bf16.h>
#include <math_constants.h>
#include <cstdint>

#define MAXN 50000
#define MAXE 500000
#define C    128
#define RELS 3

// ---------------- scratch (static device memory; no allocation) ----------------
__device__ __align__(16) float g_xw[(size_t)RELS * MAXN * C];
__device__ __align__(16) float g_h[(size_t)MAXN * C];
__device__ float g_alpha[MAXE];
__device__ float g_sq[RELS * MAXN];
__device__ float g_sk[RELS * MAXN];
__device__ __align__(16) float g_wq[RELS * C];
__device__ __align__(16) float g_wk[RELS * C];
__device__ float g_cattr;
__device__ __align__(16) __nv_bfloat16 g_wt_hi[RELS * C * C];  // W^T split hi [r][n][k]
__device__ __align__(16) __nv_bfloat16 g_wt_lo[RELS * C * C];  // W^T split lo [r][n][k]
__device__ int   g_deg[MAXN];
__device__ int   g_incl[MAXN];
__device__ int   g_indptr[MAXN + 1];
__device__ int   g_cursor[MAXN];
__device__ int   g_eidx[MAXE];
__device__ int   g_bsum[64];

__device__ __forceinline__ uint32_t smem_u32(const void* p) {
    uint32_t a;
    asm("{ .reg .u64 t; cvta.to.shared.u64 t, %1; cvt.u32.u64 %0, t; }" : "=r"(a) : "l"(p));
    return a;
}
__device__ __forceinline__ void mma_bf16(float* c, const uint32_t* a, const uint32_t* b) {
    asm volatile(
        "mma.sync.aligned.m16n8k16.row.col.f32.bf16.bf16.f32 "
        "{%0,%1,%2,%3}, {%4,%5,%6,%7}, {%8,%9}, {%0,%1,%2,%3};"
        : "+f"(c[0]), "+f"(c[1]), "+f"(c[2]), "+f"(c[3])
        : "r"(a[0]), "r"(a[1]), "r"(a[2]), "r"(a[3]), "r"(b[0]), "r"(b[1]));
}
__device__ __forceinline__ void ldsm_x4(uint32_t* r, uint32_t addr) {
    asm volatile("ldmatrix.sync.aligned.m8n8.x4.shared.b16 {%0,%1,%2,%3}, [%4];"
                 : "=r"(r[0]), "=r"(r[1]), "=r"(r[2]), "=r"(r[3]) : "r"(addr));
}

// ---------------- CSR build ----------------
__global__ void k_zero_deg(int n) {
    int i = blockIdx.x * blockDim.x + threadIdx.x;
    if (i < n) g_deg[i] = 0;
}
__global__ void k_count(const int* __restrict__ dst, int e_cnt) {
    int e = blockIdx.x * blockDim.x + threadIdx.x;
    if (e < e_cnt) atomicAdd(&g_deg[dst[e]], 1);
}
__global__ void k_scanA(int n) {
    __shared__ int sh[2][1024];
    int tid = threadIdx.x;
    int i = blockIdx.x * 1024 + tid;
    int v = (i < n) ? g_deg[i] : 0;
    sh[0][tid] = v;
    __syncthreads();
    int pb = 0;
#pragma unroll
    for (int off = 1; off < 1024; off <<= 1) {
        int nb = pb ^ 1;
        int val = sh[pb][tid];
        if (tid >= off) val += sh[pb][tid - off];
        sh[nb][tid] = val;
        pb = nb;
        __syncthreads();
    }
    int incl = sh[pb][tid];
    if (i < n) g_incl[i] = incl;
    if (tid == 1023) g_bsum[blockIdx.x] = incl;
}
__global__ void k_scanB(int nblk) {
    __shared__ int sh[64];
    int t = threadIdx.x;
    int v = (t < nblk) ? g_bsum[t] : 0;
    sh[t] = v;
    __syncthreads();
#pragma unroll
    for (int off = 1; off < 64; off <<= 1) {
        int add = (t >= off) ? sh[t - off] : 0;
        __syncthreads();
        sh[t] += add;
        __syncthreads();
    }
    if (t < nblk) g_bsum[t] = sh[t] - v;
}
__global__ void k_scanC(int n) {
    int i = blockIdx.x * blockDim.x + threadIdx.x;
    if (i < n) {
        int total = g_incl[i] + g_bsum[i >> 10];
        g_indptr[i + 1] = total;
        g_cursor[i] = total - g_deg[i];
        if (i == 0) g_indptr[0] = 0;
    }
}
__global__ void k_fill(const int* __restrict__ dst, int e_cnt) {
    int e = blockIdx.x * blockDim.x + threadIdx.x;
    if (e < e_cnt) {
        int pos = atomicAdd(&g_cursor[dst[e]], 1);
        g_eidx[pos] = e;
    }
}

// ---------------- per-layer precompute ----------------
__global__ void k_prep(const float* __restrict__ w, const float* __restrict__ q,
                       const float* __restrict__ kk, const float* __restrict__ le,
                       const float* __restrict__ ee) {
    int gw = (blockIdx.x * blockDim.x + threadIdx.x) >> 5;
    int lane = threadIdx.x & 31;
    if (gw < RELS * C) {
        const float4* row = (const float4*)(w + (size_t)gw * C);
        float4 wv = row[lane];
        float4 qv = ((const float4*)q)[lane];
        float4 kv = ((const float4*)kk)[lane];
        float aq = wv.x * qv.x + wv.y * qv.y + wv.z * qv.z + wv.w * qv.w;
        float ak = wv.x * kv.x + wv.y * kv.y + wv.z * kv.z + wv.w * kv.w;
#pragma unroll
        for (int off = 16; off; off >>= 1) {
            aq += __shfl_xor_sync(0xffffffffu, aq, off);
            ak += __shfl_xor_sync(0xffffffffu, ak, off);
        }
        if (lane == 0) { g_wq[gw] = aq; g_wk[gw] = ak; }
    } else if (gw == RELS * C) {
        float p = 0.f;
        for (int o = lane; o < C; o += 32) p += le[o] * ee[o];
#pragma unroll
        for (int off = 16; off; off >>= 1) p += __shfl_xor_sync(0xffffffffu, p, off);
        if (lane == 0) g_cattr = p;
    }
}

// transpose + bf16-split W: g_wt_*[r][n][k] from W[r][k][n]
__global__ void k_prepw(const float* __restrict__ W) {
    int r = blockIdx.x;
    const float* Wr = W + (size_t)r * C * C;
    for (int idx = threadIdx.x; idx < C * C; idx += blockDim.x) {
        int k = idx >> 7, nn = idx & 127;
        float v = Wr[idx];
        __nv_bfloat16 h = __float2bfloat16(v);
        float lo = v - __bfloat162float(h);
        g_wt_hi[(size_t)r * C * C + nn * C + k] = h;
        g_wt_lo[(size_t)r * C * C + nn * C + k] = __float2bfloat16(lo);
    }
}

// ---------------- per-node attention scalars ----------------
__global__ void k_sqk(const float* __restrict__ x, int n) {
    int gw = (blockIdx.x * blockDim.x + threadIdx.x) >> 5;
    int lane = threadIdx.x & 31;
    if (gw >= n) return;
    float4 xv = ((const float4*)x)[(size_t)gw * 32 + lane];
    float aq[RELS], ak[RELS];
#pragma unroll
    for (int r = 0; r < RELS; ++r) {
        float4 wqv = ((const float4*)g_wq)[r * 32 + lane];
        float4 wkv = ((const float4*)g_wk)[r * 32 + lane];
        aq[r] = xv.x * wqv.x + xv.y * wqv.y + xv.z * wqv.z + xv.w * wqv.w;
        ak[r] = xv.x * wkv.x + xv.y * wkv.y + xv.z * wkv.z + xv.w * wkv.w;
    }
#pragma unroll
    for (int off = 16; off; off >>= 1) {
#pragma unroll
        for (int r = 0; r < RELS; ++r) {
            aq[r] += __shfl_xor_sync(0xffffffffu, aq[r], off);
            ak[r] += __shfl_xor_sync(0xffffffffu, ak[r], off);
        }
    }
    if (lane == 0) {
#pragma unroll
        for (int r = 0; r < RELS; ++r) {
            g_sq[r * n + gw] = aq[r];
            g_sk[r * n + gw] = ak[r];
        }
    }
}

// ---------------- HMMA bf16 3-term GEMM with ldmatrix: g_xw[r] = X @ W[r] ----------------
// CTA: 256 thr (8 warps), tile M=128 x N=128. B resident full-K; A chunked K=64. 2 CTAs/SM.
#define APADB 72    // A smem stride (bf16 el): 9x16B groups/row -> conflict-free LDSM
#define BSTR  136   // B smem stride (bf16 el): 17x16B groups/row -> conflict-free LDSM
#define GEMM_SMEM (2 * 128 * BSTR * 2 + 2 * 128 * APADB * 2)

__global__ __launch_bounds__(256, 2) void k_gemm_bf(const float* __restrict__ X, int n) {
    extern __shared__ __nv_bfloat16 smb[];
    __nv_bfloat16* Bh = smb;
    __nv_bfloat16* Bl = Bh + 128 * BSTR;
    __nv_bfloat16* Ah = Bl + 128 * BSTR;
    __nv_bfloat16* Al = Ah + 128 * APADB;

    int r = blockIdx.y;
    int m0 = blockIdx.x * 128;
    float* Cr = g_xw + ((size_t)r * n) * C;
    const __nv_bfloat16* WTh = g_wt_hi + (size_t)r * C * C;
    const __nv_bfloat16* WTl = g_wt_lo + (size_t)r * C * C;

    int tid = threadIdx.x;
    int lane = tid & 31;
    int wid = tid >> 5;
    int wm = wid & 1;       // 64-row half
    int wn = wid >> 1;      // 32-col quarter

    uint32_t aAh = smem_u32(Ah), aAl = smem_u32(Al);
    uint32_t aBh = smem_u32(Bh), aBl = smem_u32(Bl);

    int lrow = (lane & 7) + ((lane >> 3) & 1) * 8;
    int lkoff = (lane >> 4) * 8;
    uint32_t baseA = (uint32_t)((wm * 64 + lrow) * APADB + lkoff) * 2;
    uint32_t baseB = (uint32_t)((wn * 32 + lrow) * BSTR + lkoff) * 2;

    // ---- load B once (full K=128, pre-split bf16 [n][k]) ----
    {
        int k4 = (lane) * 4;            // 0..124
        int nb = wid;                   // 8 warps -> 8 n rows per iter
#pragma unroll
        for (int it = 0; it < 16; ++it) {
            int nn = nb + it * 8;
            uint2 vh = *(const uint2*)(WTh + (size_t)nn * C + k4);
            uint2 vl = *(const uint2*)(WTl + (size_t)nn * C + k4);
            *(uint2*)(Bh + nn * BSTR + k4) = vh;
            *(uint2*)(Bl + nn * BSTR + k4) = vl;
        }
    }

    float acc[4][4][4];
#pragma unroll
    for (int a = 0; a < 4; ++a)
#pragma unroll
        for (int b = 0; b < 4; ++b)
#pragma unroll
            for (int cc = 0; cc < 4; ++cc) acc[a][b][cc] = 0.f;

    for (int kc = 0; kc < C; kc += 64) {
        // ---- load + split A: 128 rows x 64 k fp32 -> bf16 hi/lo ----
        {
            int k4 = (tid & 15) * 4;
            int rb = tid >> 4;
#pragma unroll
            for (int it = 0; it < 8; ++it) {
                int row = rb + it * 16;
                float4 v = make_float4(0.f, 0.f, 0.f, 0.f);
                if (m0 + row < n)
                    v = *(const float4*)(X + (size_t)(m0 + row) * C + kc + k4);
                __nv_bfloat16 hx = __float2bfloat16(v.x), hy = __float2bfloat16(v.y);
                __nv_bfloat16 hz = __float2bfloat16(v.z), hw = __float2bfloat16(v.w);
                __nv_bfloat162 h01 = __nv_bfloat162(hx, hy);
                __nv_bfloat162 h23 = __nv_bfloat162(hz, hw);
                __nv_bfloat162 l01 = __nv_bfloat162(__float2bfloat16(v.x - __bfloat162float(hx)),
                                                    __float2bfloat16(v.y - __bfloat162float(hy)));
                __nv_bfloat162 l23 = __nv_bfloat162(__float2bfloat16(v.z - __bfloat162float(hz)),
                                                    __float2bfloat16(v.w - __bfloat162float(hw)));
                *(__nv_bfloat162*)(Ah + row * APADB + k4)     = h01;
                *(__nv_bfloat162*)(Ah + row * APADB + k4 + 2) = h23;
                *(__nv_bfloat162*)(Al + row * APADB + k4)     = l01;
                *(__nv_bfloat162*)(Al + row * APADB + k4 + 2) = l23;
            }
        }
        __syncthreads();

#pragma unroll
        for (int ks = 0; ks < 4; ++ks) {
            uint32_t koffA = (uint32_t)(ks * 16) * 2;
            uint32_t koffB = (uint32_t)(kc + ks * 16) * 2;
            uint32_t ah[4][4], al[4][4], bh[4][2], bl[4][2];
#pragma unroll
            for (int mt = 0; mt < 4; ++mt) {
                ldsm_x4(ah[mt], aAh + baseA + koffA + (uint32_t)(mt * 16 * APADB * 2));
                ldsm_x4(al[mt], aAl + baseA + koffA + (uint32_t)(mt * 16 * APADB * 2));
            }
#pragma unroll
            for (int p = 0; p < 2; ++p) {
                uint32_t t4[4];
                ldsm_x4(t4, aBh + baseB + koffB + (uint32_t)(p * 16 * BSTR * 2));
                bh[2 * p][0] = t4[0]; bh[2 * p + 1][0] = t4[1];
                bh[2 * p][1] = t4[2]; bh[2 * p + 1][1] = t4[3];
                ldsm_x4(t4, aBl + baseB + koffB + (uint32_t)(p * 16 * BSTR * 2));
                bl[2 * p][0] = t4[0]; bl[2 * p + 1][0] = t4[1];
                bl[2 * p][1] = t4[2]; bl[2 * p + 1][1] = t4[3];
            }
#pragma unroll
            for (int mt = 0; mt < 4; ++mt)
#pragma unroll
                for (int nt = 0; nt < 4; ++nt) mma_bf16(acc[mt][nt], ah[mt], bh[nt]);
#pragma unroll
            for (int mt = 0; mt < 4; ++mt)
#pragma unroll
                for (int nt = 0; nt < 4; ++nt) mma_bf16(acc[mt][nt], ah[mt], bl[nt]);
#pragma unroll
            for (int mt = 0; mt < 4; ++mt)
#pragma unroll
                for (int nt = 0; nt < 4; ++nt) mma_bf16(acc[mt][nt], al[mt], bh[nt]);
        }
        __syncthreads();
    }

    // ---- epilogue ----
#pragma unroll
    for (int mt = 0; mt < 4; ++mt) {
        int row0 = m0 + wm * 64 + mt * 16 + (lane >> 2);
        int row1 = row0 + 8;
#pragma unroll
        for (int nt = 0; nt < 4; ++nt) {
            int col = wn * 32 + nt * 8 + 2 * (lane & 3);
            if (row0 < n)
                *(float2*)(Cr + (size_t)row0 * C + col) = make_float2(acc[mt][nt][0], acc[mt][nt][1]);
            if (row1 < n)
                *(float2*)(Cr + (size_t)row1 * C + col) = make_float2(acc[mt][nt][2], acc[mt][nt][3]);
        }
    }
}

// ---------------- per-edge attention logits ----------------
__global__ void k_alpha(const int* __restrict__ src, const int* __restrict__ dst,
                        const int* __restrict__ etype, const float* __restrict__ attr,
                        int n, int e_cnt) {
    int e = blockIdx.x * blockDim.x + threadIdx.x;
    if (e >= e_cnt) return;
    int r = etype[e];
    float a = g_sq[r * n + dst[e]] + g_sk[r * n + src[e]] + g_cattr * attr[e];
    g_alpha[e] = (a > 0.f) ? a : 0.2f * a;
}

// ---------------- per-node softmax + weighted aggregation (warp per node) ----------------
__global__ void k_agg(const int* __restrict__ src, const int* __restrict__ etype,
                      const float* __restrict__ bias, float* __restrict__ out,
                      int relu, int n) {
    int gw = (blockIdx.x * blockDim.x + threadIdx.x) >> 5;
    int lane = threadIdx.x & 31;
    if (gw >= n) return;
    int beg = g_indptr[gw], end = g_indptr[gw + 1];

    float m = -CUDART_INF_F;
    for (int j = beg + lane; j < end; j += 32) m = fmaxf(m, g_alpha[g_eidx[j]]);
#pragma unroll
    for (int off = 16; off; off >>= 1) m = fmaxf(m, __shfl_xor_sync(0xffffffffu, m, off));

    float s = 0.f;
    for (int j = beg + lane; j < end; j += 32) s += __expf(g_alpha[g_eidx[j]] - m);
#pragma unroll
    for (int off = 16; off; off >>= 1) s += __shfl_xor_sync(0xffffffffu, s, off);
    float inv = 1.f / (s + 1e-16f);

    float4 acc = make_float4(0.f, 0.f, 0.f, 0.f);
    for (int j = beg; j < end; ++j) {
        int e = g_eidx[j];
        float coeff = __expf(g_alpha[e] - m) * inv;
        int sv = src[e];
        int r = etype[e];
        const float4* row = (const float4*)(g_xw + ((size_t)r * n + sv) * C);
        float4 v = row[lane];
        acc.x = fmaf(coeff, v.x, acc.x);
        acc.y = fmaf(coeff, v.y, acc.y);
        acc.z = fmaf(coeff, v.z, acc.z);
        acc.w = fmaf(coeff, v.w, acc.w);
    }
    float4 bb = ((const float4*)bias)[lane];
    acc.x += bb.x; acc.y += bb.y; acc.z += bb.z; acc.w += bb.w;
    if (relu) {
        acc.x = fmaxf(acc.x, 0.f); acc.y = fmaxf(acc.y, 0.f);
        acc.z = fmaxf(acc.z, 0.f); acc.w = fmaxf(acc.w, 0.f);
    }
    ((float4*)(out + (size_t)gw * C))[lane] = acc;
}

// ---------------- driver ----------------
extern "C" void kernel_launch(void* const* d_in, const int* in_sizes, int n_in,
                              void* d_out, int out_size) {
    const float* x    = (const float*)d_in[0];
    const int*   ei   = (const int*)d_in[1];
    const int*   et   = (const int*)d_in[2];
    const float* attr = (const float*)d_in[3];
    const float *w1 = (const float*)d_in[4],  *q1 = (const float*)d_in[5],
                *k1 = (const float*)d_in[6],  *le1 = (const float*)d_in[7],
                *e1 = (const float*)d_in[8],  *b1 = (const float*)d_in[9];
    const float *w2 = (const float*)d_in[10], *q2 = (const float*)d_in[11],
                *k2 = (const float*)d_in[12], *le2 = (const float*)d_in[13],
                *e2 = (const float*)d_in[14], *b2 = (const float*)d_in[15];

    int n = in_sizes[0] / C;
    int e_cnt = in_sizes[2];
    const int* src = ei;
    const int* dst = ei + e_cnt;

    float* h = nullptr;
    cudaGetSymbolAddress((void**)&h, g_h);

    static bool attr_set = false;
    if (!attr_set) {
        cudaFuncSetAttribute(k_gemm_bf, cudaFuncAttributeMaxDynamicSharedMemorySize, GEMM_SMEM);
        attr_set = true;
    }

    dim3 gg((n + 127) / 128, RELS);
    int nblk = (n + 1023) / 1024;
    int prep_blocks = (RELS * C + 1 + 7) / 8;

    // launch #4 = k_gemm_bf (profiled slot)
    k_prepw<<<RELS, 256>>>(w1);
    k_zero_deg<<<(n + 255) / 256, 256>>>(n);
    k_count<<<(e_cnt + 255) / 256, 256>>>(dst, e_cnt);
    k_gemm_bf<<<gg, 256, GEMM_SMEM>>>(x, n);
    k_scanA<<<nblk, 1024>>>(n);
    k_scanB<<<1, 64>>>(nblk);
    k_scanC<<<(n + 255) / 256, 256>>>(n);
    k_fill<<<(e_cnt + 255) / 256, 256>>>(dst, e_cnt);

    // layer 1 attention + aggregation
    k_prep<<<prep_blocks, 256>>>(w1, q1, k1, le1, e1);
    k_sqk<<<(n + 7) / 8, 256>>>(x, n);
    k_alpha<<<(e_cnt + 255) / 256, 256>>>(src, dst, et, attr, n, e_cnt);
    k_agg<<<(n + 7) / 8, 256>>>(src, et, b1, h, 1, n);

    // layer 2
    k_prepw<<<RELS, 256>>>(w2);
    k_gemm_bf<<<gg, 256, GEMM_SMEM>>>(h, n);
    k_prep<<<prep_blocks, 256>>>(w2, q2, k2, le2, e2);
    k_sqk<<<(n + 7) / 8, 256>>>(h, n);
    k_alpha<<<(e_cnt + 255) / 256, 256>>>(src, dst, et, attr, n, e_cnt);
    k_agg<<<(n + 7) / 8, 256>>>(src, et, b2, (float*)d_out, 0, n);
}

// round 8
// speedup vs baseline: 1.4082x; 1.0248x over previous
#include <cuda_runtime.h>
#include <cuda_bf16.h>
#include <math_constants.h>
#include <cstdint>

#define MAXN 50000
#define MAXE 500000
#define C    128
#define RELS 3
#define KS   (RELS * C)   // 384 stacked K

// ---------------- scratch (static device memory; no allocation) ----------------
__device__ __align__(16) float g_agg[(size_t)MAXN * KS];   // per-node aggregated x, [n][r*128+c]
__device__ __align__(16) float g_h[(size_t)MAXN * C];      // layer-1 output
__device__ float g_alphac[MAXE];                            // alpha in CSR order
__device__ unsigned g_pack[MAXE];                           // (r<<28)|src in CSR order
__device__ float g_sq[RELS * MAXN];
__device__ float g_sk[RELS * MAXN];
__device__ __align__(16) float g_wq[RELS * C];
__device__ __align__(16) float g_wk[RELS * C];
__device__ float g_cattr;
__device__ __align__(16) __nv_bfloat16 g_wts_hi[C * KS];   // stacked W^T hi: [nout][r*128+kin]
__device__ __align__(16) __nv_bfloat16 g_wts_lo[C * KS];
__device__ int g_deg[MAXN];          // zero-init; re-zeroed by k_scanC each run
__device__ int g_incl[MAXN];
__device__ int g_indptr[MAXN + 1];
__device__ int g_cursor[MAXN];
__device__ int g_bsum[64];

__device__ __forceinline__ uint32_t smem_u32(const void* p) {
    uint32_t a;
    asm("{ .reg .u64 t; cvta.to.shared.u64 t, %1; cvt.u32.u64 %0, t; }" : "=r"(a) : "l"(p));
    return a;
}
__device__ __forceinline__ void mma_bf16(float* c, const uint32_t* a, const uint32_t* b) {
    asm volatile(
        "mma.sync.aligned.m16n8k16.row.col.f32.bf16.bf16.f32 "
        "{%0,%1,%2,%3}, {%4,%5,%6,%7}, {%8,%9}, {%0,%1,%2,%3};"
        : "+f"(c[0]), "+f"(c[1]), "+f"(c[2]), "+f"(c[3])
        : "r"(a[0]), "r"(a[1]), "r"(a[2]), "r"(a[3]), "r"(b[0]), "r"(b[1]));
}
__device__ __forceinline__ void ldsm_x4(uint32_t* r, uint32_t addr) {
    asm volatile("ldmatrix.sync.aligned.m8n8.x4.shared.b16 {%0,%1,%2,%3}, [%4];"
                 : "=r"(r[0]), "=r"(r[1]), "=r"(r[2]), "=r"(r[3]) : "r"(addr));
}

// ---------------- CSR build ----------------
__global__ void k_count(const int* __restrict__ dst, int e_cnt) {
    int e = blockIdx.x * blockDim.x + threadIdx.x;
    if (e < e_cnt) atomicAdd(&g_deg[dst[e]], 1);
}
__global__ void k_scanA(int n) {
    __shared__ int sh[2][1024];
    int tid = threadIdx.x;
    int i = blockIdx.x * 1024 + tid;
    int v = (i < n) ? g_deg[i] : 0;
    sh[0][tid] = v;
    __syncthreads();
    int pb = 0;
#pragma unroll
    for (int off = 1; off < 1024; off <<= 1) {
        int nb = pb ^ 1;
        int val = sh[pb][tid];
        if (tid >= off) val += sh[pb][tid - off];
        sh[nb][tid] = val;
        pb = nb;
        __syncthreads();
    }
    int incl = sh[pb][tid];
    if (i < n) g_incl[i] = incl;
    if (tid == 1023) g_bsum[blockIdx.x] = incl;
}
// finalize: scan bsum in-block, write indptr + cursor, zero deg for next replay
__global__ void k_scanC(int n, int nblk) {
    __shared__ int sb[64];
    int tid = threadIdx.x;
    int bid = blockIdx.x;
    if (tid < 64) sb[tid] = (tid < nblk) ? g_bsum[tid] : 0;
    __syncthreads();
#pragma unroll
    for (int off = 1; off < 64; off <<= 1) {
        int add = (tid < 64 && tid >= off) ? sb[tid - off] : 0;
        __syncthreads();
        if (tid < 64) sb[tid] += add;
        __syncthreads();
    }
    int base = (bid == 0) ? 0 : sb[bid - 1];
    int i = bid * 1024 + tid;
    if (i < n) {
        int total = g_incl[i] + base;
        g_indptr[i + 1] = total;
        g_cursor[i] = total - g_deg[i];
        g_deg[i] = 0;
        if (i == 0) g_indptr[0] = 0;
    }
}

// ---------------- per-layer precompute (merged prep + stacked W split) ----------------
// blocks 0..RELS-1: W^T bf16 split into stacked layout; blocks >= RELS: wq/wk/cattr
__global__ void k_prepall(const float* __restrict__ w, const float* __restrict__ q,
                          const float* __restrict__ kk, const float* __restrict__ le,
                          const float* __restrict__ ee) {
    if (blockIdx.x < RELS) {
        int r = blockIdx.x;
        const float* Wr = w + (size_t)r * C * C;
        for (int idx = threadIdx.x; idx < C * C; idx += blockDim.x) {
            int k = idx >> 7, nn = idx & 127;
            float v = Wr[idx];
            __nv_bfloat16 h = __float2bfloat16(v);
            float lo = v - __bfloat162float(h);
            g_wts_hi[(size_t)nn * KS + r * C + k] = h;
            g_wts_lo[(size_t)nn * KS + r * C + k] = __float2bfloat16(lo);
        }
        return;
    }
    int gw = (blockIdx.x - RELS) * 8 + (threadIdx.x >> 5);
    int lane = threadIdx.x & 31;
    if (gw < RELS * C) {
        const float4* row = (const float4*)(w + (size_t)gw * C);
        float4 wv = row[lane];
        float4 qv = ((const float4*)q)[lane];
        float4 kv = ((const float4*)kk)[lane];
        float aq = wv.x * qv.x + wv.y * qv.y + wv.z * qv.z + wv.w * qv.w;
        float ak = wv.x * kv.x + wv.y * kv.y + wv.z * kv.z + wv.w * kv.w;
#pragma unroll
        for (int off = 16; off; off >>= 1) {
            aq += __shfl_xor_sync(0xffffffffu, aq, off);
            ak += __shfl_xor_sync(0xffffffffu, ak, off);
        }
        if (lane == 0) { g_wq[gw] = aq; g_wk[gw] = ak; }
    } else if (gw == RELS * C) {
        float p = 0.f;
        for (int o = lane; o < C; o += 32) p += le[o] * ee[o];
#pragma unroll
        for (int off = 16; off; off >>= 1) p += __shfl_xor_sync(0xffffffffu, p, off);
        if (lane == 0) g_cattr = p;
    }
}

// ---------------- per-node attention scalars ----------------
__global__ void k_sqk(const float* __restrict__ x, int n) {
    int gw = (blockIdx.x * blockDim.x + threadIdx.x) >> 5;
    int lane = threadIdx.x & 31;
    if (gw >= n) return;
    float4 xv = ((const float4*)x)[(size_t)gw * 32 + lane];
    float aq[RELS], ak[RELS];
#pragma unroll
    for (int r = 0; r < RELS; ++r) {
        float4 wqv = ((const float4*)g_wq)[r * 32 + lane];
        float4 wkv = ((const float4*)g_wk)[r * 32 + lane];
        aq[r] = xv.x * wqv.x + xv.y * wqv.y + xv.z * wqv.z + xv.w * wqv.w;
        ak[r] = xv.x * wkv.x + xv.y * wkv.y + xv.z * wkv.z + xv.w * wkv.w;
    }
#pragma unroll
    for (int off = 16; off; off >>= 1) {
#pragma unroll
        for (int r = 0; r < RELS; ++r) {
            aq[r] += __shfl_xor_sync(0xffffffffu, aq[r], off);
            ak[r] += __shfl_xor_sync(0xffffffffu, ak[r], off);
        }
    }
    if (lane == 0) {
#pragma unroll
        for (int r = 0; r < RELS; ++r) {
            g_sq[r * n + gw] = aq[r];
            g_sk[r * n + gw] = ak[r];
        }
    }
}

// ---------------- fused: compute alpha + scatter into CSR slots ----------------
__global__ void k_fillalpha(const int* __restrict__ src, const int* __restrict__ dst,
                            const int* __restrict__ etype, const float* __restrict__ attr,
                            int n, int e_cnt) {
    int e = blockIdx.x * blockDim.x + threadIdx.x;
    if (e >= e_cnt) return;
    int s = src[e], d = dst[e], r = etype[e];
    float a = g_sq[r * n + d] + g_sk[r * n + s] + g_cattr * attr[e];
    a = (a > 0.f) ? a : 0.2f * a;
    int pos = atomicAdd(&g_cursor[d], 1);
    g_alphac[pos] = a;
    g_pack[pos] = (unsigned)s | ((unsigned)r << 28);
}

// ---------------- per-node softmax + aggregate raw x into g_agg; reset cursor ----------------
__global__ void k_agg(const float* __restrict__ xin, int n) {
    int gw = (blockIdx.x * blockDim.x + threadIdx.x) >> 5;
    int lane = threadIdx.x & 31;
    if (gw >= n) return;
    int beg = g_indptr[gw], end = g_indptr[gw + 1];

    float m = -CUDART_INF_F;
    for (int j = beg + lane; j < end; j += 32) m = fmaxf(m, g_alphac[j]);
#pragma unroll
    for (int off = 16; off; off >>= 1) m = fmaxf(m, __shfl_xor_sync(0xffffffffu, m, off));

    float s = 0.f;
    for (int j = beg + lane; j < end; j += 32) s += __expf(g_alphac[j] - m);
#pragma unroll
    for (int off = 16; off; off >>= 1) s += __shfl_xor_sync(0xffffffffu, s, off);
    float inv = 1.f / (s + 1e-16f);

    float4 a0 = make_float4(0.f, 0.f, 0.f, 0.f);
    float4 a1 = a0, a2 = a0;
    for (int j = beg; j < end; ++j) {
        float co = __expf(g_alphac[j] - m) * inv;
        unsigned p = g_pack[j];
        unsigned sv = p & 0x0FFFFFFFu;
        unsigned r = p >> 28;
        float4 v = ((const float4*)(xin + (size_t)sv * C))[lane];
        if (r == 0) {
            a0.x = fmaf(co, v.x, a0.x); a0.y = fmaf(co, v.y, a0.y);
            a0.z = fmaf(co, v.z, a0.z); a0.w = fmaf(co, v.w, a0.w);
        } else if (r == 1) {
            a1.x = fmaf(co, v.x, a1.x); a1.y = fmaf(co, v.y, a1.y);
            a1.z = fmaf(co, v.z, a1.z); a1.w = fmaf(co, v.w, a1.w);
        } else {
            a2.x = fmaf(co, v.x, a2.x); a2.y = fmaf(co, v.y, a2.y);
            a2.z = fmaf(co, v.z, a2.z); a2.w = fmaf(co, v.w, a2.w);
        }
    }
    float* ob = g_agg + (size_t)gw * KS;
    ((float4*)(ob))[lane]       = a0;
    ((float4*)(ob + C))[lane]   = a1;
    ((float4*)(ob + 2 * C))[lane] = a2;
    if (lane == 0) g_cursor[gw] = beg;   // reset for next layer's fill
}

// ---------------- stacked HMMA bf16 3-term GEMM: out = agg @ Wstack + bias (opt relu) ----------------
// CTA: 256 thr (8 warps), tile M=128 x N=128, K=384 in 6 chunks of 64. 2 CTAs/SM.
#define APADB 72
#define GEMM_SMEM (4 * 128 * APADB * 2)

__global__ __launch_bounds__(256, 2) void k_gemm_st(const float* __restrict__ A,
                                                    const float* __restrict__ bias,
                                                    float* __restrict__ out,
                                                    int relu, int n) {
    extern __shared__ __nv_bfloat16 smb[];
    __nv_bfloat16* Ah = smb;
    __nv_bfloat16* Al = Ah + 128 * APADB;
    __nv_bfloat16* Bh = Al + 128 * APADB;
    __nv_bfloat16* Bl = Bh + 128 * APADB;

    int m0 = blockIdx.x * 128;
    int tid = threadIdx.x;
    int lane = tid & 31;
    int wid = tid >> 5;
    int wm = wid & 1;
    int wn = wid >> 1;

    uint32_t aAh = smem_u32(Ah), aAl = smem_u32(Al);
    uint32_t aBh = smem_u32(Bh), aBl = smem_u32(Bl);

    int lrow = (lane & 7) + ((lane >> 3) & 1) * 8;
    int lkoff = (lane >> 4) * 8;
    uint32_t baseA = (uint32_t)((wm * 64 + lrow) * APADB + lkoff) * 2;
    uint32_t baseB = (uint32_t)((wn * 32 + lrow) * APADB + lkoff) * 2;

    float acc[4][4][4];
#pragma unroll
    for (int a = 0; a < 4; ++a)
#pragma unroll
        for (int b = 0; b < 4; ++b)
#pragma unroll
            for (int cc = 0; cc < 4; ++cc) acc[a][b][cc] = 0.f;

#pragma unroll 1
    for (int kc = 0; kc < KS; kc += 64) {
        // A: 128 rows x 64 k fp32 -> split bf16
        {
            int k4 = (tid & 15) * 4;
            int rb = tid >> 4;
#pragma unroll
            for (int it = 0; it < 8; ++it) {
                int row = rb + it * 16;
                float4 v = make_float4(0.f, 0.f, 0.f, 0.f);
                if (m0 + row < n)
                    v = *(const float4*)(A + (size_t)(m0 + row) * KS + kc + k4);
                __nv_bfloat16 hx = __float2bfloat16(v.x), hy = __float2bfloat16(v.y);
                __nv_bfloat16 hz = __float2bfloat16(v.z), hw = __float2bfloat16(v.w);
                *(__nv_bfloat162*)(Ah + row * APADB + k4)     = __nv_bfloat162(hx, hy);
                *(__nv_bfloat162*)(Ah + row * APADB + k4 + 2) = __nv_bfloat162(hz, hw);
                *(__nv_bfloat162*)(Al + row * APADB + k4) =
                    __nv_bfloat162(__float2bfloat16(v.x - __bfloat162float(hx)),
                                   __float2bfloat16(v.y - __bfloat162float(hy)));
                *(__nv_bfloat162*)(Al + row * APADB + k4 + 2) =
                    __nv_bfloat162(__float2bfloat16(v.z - __bfloat162float(hz)),
                                   __float2bfloat16(v.w - __bfloat162float(hw)));
            }
        }
        // B: 128 nout rows x 64 k (pre-split bf16 stacked)
        {
            int k4 = (tid & 15) * 4;
            int nb = tid >> 4;
#pragma unroll
            for (int it = 0; it < 8; ++it) {
                int nn = nb + it * 16;
                uint2 vh = *(const uint2*)(g_wts_hi + (size_t)nn * KS + kc + k4);
                uint2 vl = *(const uint2*)(g_wts_lo + (size_t)nn * KS + kc + k4);
                *(uint2*)(Bh + nn * APADB + k4) = vh;
                *(uint2*)(Bl + nn * APADB + k4) = vl;
            }
        }
        __syncthreads();

#pragma unroll
        for (int ks = 0; ks < 4; ++ks) {
            uint32_t koff = (uint32_t)(ks * 16) * 2;
            uint32_t ah[4][4], al[4][4], bh[4][2], bl[4][2];
#pragma unroll
            for (int mt = 0; mt < 4; ++mt) {
                ldsm_x4(ah[mt], aAh + baseA + koff + (uint32_t)(mt * 16 * APADB * 2));
                ldsm_x4(al[mt], aAl + baseA + koff + (uint32_t)(mt * 16 * APADB * 2));
            }
#pragma unroll
            for (int p = 0; p < 2; ++p) {
                uint32_t t4[4];
                ldsm_x4(t4, aBh + baseB + koff + (uint32_t)(p * 16 * APADB * 2));
                bh[2 * p][0] = t4[0]; bh[2 * p + 1][0] = t4[1];
                bh[2 * p][1] = t4[2]; bh[2 * p + 1][1] = t4[3];
                ldsm_x4(t4, aBl + baseB + koff + (uint32_t)(p * 16 * APADB * 2));
                bl[2 * p][0] = t4[0]; bl[2 * p + 1][0] = t4[1];
                bl[2 * p][1] = t4[2]; bl[2 * p + 1][1] = t4[3];
            }
#pragma unroll
            for (int mt = 0; mt < 4; ++mt)
#pragma unroll
                for (int nt = 0; nt < 4; ++nt) mma_bf16(acc[mt][nt], ah[mt], bh[nt]);
#pragma unroll
            for (int mt = 0; mt < 4; ++mt)
#pragma unroll
                for (int nt = 0; nt < 4; ++nt) mma_bf16(acc[mt][nt], ah[mt], bl[nt]);
#pragma unroll
            for (int mt = 0; mt < 4; ++mt)
#pragma unroll
                for (int nt = 0; nt < 4; ++nt) mma_bf16(acc[mt][nt], al[mt], bh[nt]);
        }
        __syncthreads();
    }

    // ---- epilogue: + bias, optional relu ----
    float bx[4][2];
#pragma unroll
    for (int nt = 0; nt < 4; ++nt) {
        int col = wn * 32 + nt * 8 + 2 * (lane & 3);
        bx[nt][0] = bias[col];
        bx[nt][1] = bias[col + 1];
    }
#pragma unroll
    for (int mt = 0; mt < 4; ++mt) {
        int row0 = m0 + wm * 64 + mt * 16 + (lane >> 2);
        int row1 = row0 + 8;
#pragma unroll
        for (int nt = 0; nt < 4; ++nt) {
            int col = wn * 32 + nt * 8 + 2 * (lane & 3);
            float2 o0 = make_float2(acc[mt][nt][0] + bx[nt][0], acc[mt][nt][1] + bx[nt][1]);
            float2 o1 = make_float2(acc[mt][nt][2] + bx[nt][0], acc[mt][nt][3] + bx[nt][1]);
            if (relu) {
                o0.x = fmaxf(o0.x, 0.f); o0.y = fmaxf(o0.y, 0.f);
                o1.x = fmaxf(o1.x, 0.f); o1.y = fmaxf(o1.y, 0.f);
            }
            if (row0 < n) *(float2*)(out + (size_t)row0 * C + col) = o0;
            if (row1 < n) *(float2*)(out + (size_t)row1 * C + col) = o1;
        }
    }
}

// ---------------- driver ----------------
extern "C" void kernel_launch(void* const* d_in, const int* in_sizes, int n_in,
                              void* d_out, int out_size) {
    const float* x    = (const float*)d_in[0];
    const int*   ei   = (const int*)d_in[1];
    const int*   et   = (const int*)d_in[2];
    const float* attr = (const float*)d_in[3];
    const float *w1 = (const float*)d_in[4],  *q1 = (const float*)d_in[5],
                *k1 = (const float*)d_in[6],  *le1 = (const float*)d_in[7],
                *e1 = (const float*)d_in[8],  *b1 = (const float*)d_in[9];
    const float *w2 = (const float*)d_in[10], *q2 = (const float*)d_in[11],
                *k2 = (const float*)d_in[12], *le2 = (const float*)d_in[13],
                *e2 = (const float*)d_in[14], *b2 = (const float*)d_in[15];

    int n = in_sizes[0] / C;
    int e_cnt = in_sizes[2];
    const int* src = ei;
    const int* dst = ei + e_cnt;

    float* h = nullptr;
    cudaGetSymbolAddress((void**)&h, g_h);
    float* agg = nullptr;
    cudaGetSymbolAddress((void**)&agg, g_agg);

    static bool attr_set = false;
    if (!attr_set) {
        cudaFuncSetAttribute(k_gemm_st, cudaFuncAttributeMaxDynamicSharedMemorySize, GEMM_SMEM);
        attr_set = true;
    }

    int nblk = (n + 1023) / 1024;
    int prep_grid = RELS + (RELS * C + 1 + 7) / 8;
    int gemm_grid = (n + 127) / 128;

    // CSR build (3 kernels; deg starts zeroed, re-zeroed by scanC)
    k_count<<<(e_cnt + 255) / 256, 256>>>(dst, e_cnt);
    k_scanA<<<nblk, 1024>>>(n);
    k_scanC<<<nblk, 1024>>>(n, nblk);

    // layer 1
    k_prepall<<<prep_grid, 256>>>(w1, q1, k1, le1, e1);
    k_sqk<<<(n + 7) / 8, 256>>>(x, n);
    k_fillalpha<<<(e_cnt + 255) / 256, 256>>>(src, dst, et, attr, n, e_cnt);
    k_agg<<<(n + 7) / 8, 256>>>(x, n);
    k_gemm_st<<<gemm_grid, 256, GEMM_SMEM>>>(agg, b1, h, 1, n);

    // layer 2
    k_prepall<<<prep_grid, 256>>>(w2, q2, k2, le2, e2);
    k_sqk<<<(n + 7) / 8, 256>>>(h, n);
    k_fillalpha<<<(e_cnt + 255) / 256, 256>>>(src, dst, et, attr, n, e_cnt);
    k_agg<<<(n + 7) / 8, 256>>>(h, n);
    k_gemm_st<<<gemm_grid, 256, GEMM_SMEM>>>(agg, b2, (float*)d_out, 0, n);
}

// round 9
// speedup vs baseline: 1.8411x; 1.3074x over previous
#include <cuda_runtime.h>
#include <cuda_bf16.h>
#include <math_constants.h>
#include <cstdint>

#define MAXN 50000
#define MAXE 500000
#define C    128
#define RELS 3
#define KS   (RELS * C)   // 384 stacked K

// ---------------- scratch (static device memory; no allocation) ----------------
__device__ __align__(16) float g_agg[(size_t)MAXN * KS];   // per-node aggregated x, [n][r*128+c]
__device__ __align__(16) float g_h[(size_t)MAXN * C];      // layer-1 output
__device__ float g_alphac[MAXE];                            // alpha in CSR order
__device__ unsigned g_pack[MAXE];                           // (r<<28)|src in CSR order
__device__ float g_sq[RELS * MAXN];
__device__ float g_sk[RELS * MAXN];
__device__ __align__(16) float g_wq[RELS * C];
__device__ __align__(16) float g_wk[RELS * C];
__device__ float g_cattr;
__device__ __align__(16) __nv_bfloat16 g_wts_hi[C * KS];   // stacked W^T hi: [nout][r*128+kin]
__device__ __align__(16) __nv_bfloat16 g_wts_lo[C * KS];
__device__ int g_deg[MAXN];          // zero-init; re-zeroed by k_scanC each run
__device__ int g_incl[MAXN];
__device__ int g_indptr[MAXN + 1];
__device__ int g_cursor[MAXN];
__device__ int g_bsum[64];

__device__ __forceinline__ uint32_t smem_u32(const void* p) {
    uint32_t a;
    asm("{ .reg .u64 t; cvta.to.shared.u64 t, %1; cvt.u32.u64 %0, t; }" : "=r"(a) : "l"(p));
    return a;
}
__device__ __forceinline__ void mma_bf16(float* c, const uint32_t* a, const uint32_t* b) {
    asm volatile(
        "mma.sync.aligned.m16n8k16.row.col.f32.bf16.bf16.f32 "
        "{%0,%1,%2,%3}, {%4,%5,%6,%7}, {%8,%9}, {%0,%1,%2,%3};"
        : "+f"(c[0]), "+f"(c[1]), "+f"(c[2]), "+f"(c[3])
        : "r"(a[0]), "r"(a[1]), "r"(a[2]), "r"(a[3]), "r"(b[0]), "r"(b[1]));
}
__device__ __forceinline__ void ldsm_x4(uint32_t* r, uint32_t addr) {
    asm volatile("ldmatrix.sync.aligned.m8n8.x4.shared.b16 {%0,%1,%2,%3}, [%4];"
                 : "=r"(r[0]), "=r"(r[1]), "=r"(r[2]), "=r"(r[3]) : "r"(addr));
}

// ---------------- CSR build ----------------
__global__ void k_count(const int* __restrict__ dst, int e_cnt) {
    int e = blockIdx.x * blockDim.x + threadIdx.x;
    if (e < e_cnt) atomicAdd(&g_deg[dst[e]], 1);
}
__global__ void k_scanA(int n) {
    __shared__ int sh[2][1024];
    int tid = threadIdx.x;
    int i = blockIdx.x * 1024 + tid;
    int v = (i < n) ? g_deg[i] : 0;
    sh[0][tid] = v;
    __syncthreads();
    int pb = 0;
#pragma unroll
    for (int off = 1; off < 1024; off <<= 1) {
        int nb = pb ^ 1;
        int val = sh[pb][tid];
        if (tid >= off) val += sh[pb][tid - off];
        sh[nb][tid] = val;
        pb = nb;
        __syncthreads();
    }
    int incl = sh[pb][tid];
    if (i < n) g_incl[i] = incl;
    if (tid == 1023) g_bsum[blockIdx.x] = incl;
}
// finalize: scan bsum in-block, write indptr + cursor, zero deg for next replay
__global__ void k_scanC(int n, int nblk) {
    __shared__ int sb[64];
    int tid = threadIdx.x;
    int bid = blockIdx.x;
    if (tid < 64) sb[tid] = (tid < nblk) ? g_bsum[tid] : 0;
    __syncthreads();
#pragma unroll
    for (int off = 1; off < 64; off <<= 1) {
        int add = (tid < 64 && tid >= off) ? sb[tid - off] : 0;
        __syncthreads();
        if (tid < 64) sb[tid] += add;
        __syncthreads();
    }
    int base = (bid == 0) ? 0 : sb[bid - 1];
    int i = bid * 1024 + tid;
    if (i < n) {
        int total = g_incl[i] + base;
        g_indptr[i + 1] = total;
        g_cursor[i] = total - g_deg[i];
        g_deg[i] = 0;
        if (i == 0) g_indptr[0] = 0;
    }
}

// ---------------- per-layer precompute (tiled W transpose-split + wq/wk/cattr) ----------------
// blocks 0..2*RELS-1: smem-tiled transpose of one 64-k slab of W[r] -> stacked bf16 hi/lo
// blocks >= 2*RELS: wq/wk/cattr
__global__ void k_prepall(const float* __restrict__ w, const float* __restrict__ q,
                          const float* __restrict__ kk, const float* __restrict__ le,
                          const float* __restrict__ ee) {
    if (blockIdx.x < 2 * RELS) {
        __shared__ float tile[64][129];
        int r = blockIdx.x >> 1;
        int kt = (blockIdx.x & 1) * 64;
        const float* Wr = w + (size_t)r * C * C;
        int tid = threadIdx.x;
        // coalesced load: 64 k-rows x 128 nout floats
#pragma unroll
        for (int it = 0; it < 8; ++it) {
            int idx = tid + it * 256;       // float4 index, 0..2047
            int kkr = idx >> 5;             // row (k within slab)
            int nn4 = (idx & 31) * 4;
            float4 v = *(const float4*)(Wr + (size_t)(kt + kkr) * C + nn4);
            tile[kkr][nn4] = v.x; tile[kkr][nn4 + 1] = v.y;
            tile[kkr][nn4 + 2] = v.z; tile[kkr][nn4 + 3] = v.w;
        }
        __syncthreads();
        int lane = tid & 31, wid = tid >> 5;
        // coalesced write: warp per nout row, lane covers 2 k's (128B per warp-store)
        for (int nn = wid; nn < C; nn += 8) {
            float v0 = tile[2 * lane][nn];
            float v1 = tile[2 * lane + 1][nn];
            __nv_bfloat16 h0 = __float2bfloat16(v0), h1 = __float2bfloat16(v1);
            __nv_bfloat162 hh(h0, h1);
            __nv_bfloat162 ll(__float2bfloat16(v0 - __bfloat162float(h0)),
                              __float2bfloat16(v1 - __bfloat162float(h1)));
            size_t off = (size_t)nn * KS + r * C + kt + 2 * lane;
            *(__nv_bfloat162*)(g_wts_hi + off) = hh;
            *(__nv_bfloat162*)(g_wts_lo + off) = ll;
        }
        return;
    }
    int gw = (blockIdx.x - 2 * RELS) * 8 + (threadIdx.x >> 5);
    int lane = threadIdx.x & 31;
    if (gw < RELS * C) {
        const float4* row = (const float4*)(w + (size_t)gw * C);
        float4 wv = row[lane];
        float4 qv = ((const float4*)q)[lane];
        float4 kv = ((const float4*)kk)[lane];
        float aq = wv.x * qv.x + wv.y * qv.y + wv.z * qv.z + wv.w * qv.w;
        float ak = wv.x * kv.x + wv.y * kv.y + wv.z * kv.z + wv.w * kv.w;
#pragma unroll
        for (int off = 16; off; off >>= 1) {
            aq += __shfl_xor_sync(0xffffffffu, aq, off);
            ak += __shfl_xor_sync(0xffffffffu, ak, off);
        }
        if (lane == 0) { g_wq[gw] = aq; g_wk[gw] = ak; }
    } else if (gw == RELS * C) {
        float p = 0.f;
        for (int o = lane; o < C; o += 32) p += le[o] * ee[o];
#pragma unroll
        for (int off = 16; off; off >>= 1) p += __shfl_xor_sync(0xffffffffu, p, off);
        if (lane == 0) g_cattr = p;
    }
}

// ---------------- per-node attention scalars ----------------
__global__ void k_sqk(const float* __restrict__ x, int n) {
    int gw = (blockIdx.x * blockDim.x + threadIdx.x) >> 5;
    int lane = threadIdx.x & 31;
    if (gw >= n) return;
    float4 xv = ((const float4*)x)[(size_t)gw * 32 + lane];
    float aq[RELS], ak[RELS];
#pragma unroll
    for (int r = 0; r < RELS; ++r) {
        float4 wqv = ((const float4*)g_wq)[r * 32 + lane];
        float4 wkv = ((const float4*)g_wk)[r * 32 + lane];
        aq[r] = xv.x * wqv.x + xv.y * wqv.y + xv.z * wqv.z + xv.w * wqv.w;
        ak[r] = xv.x * wkv.x + xv.y * wkv.y + xv.z * wkv.z + xv.w * wkv.w;
    }
#pragma unroll
    for (int off = 16; off; off >>= 1) {
#pragma unroll
        for (int r = 0; r < RELS; ++r) {
            aq[r] += __shfl_xor_sync(0xffffffffu, aq[r], off);
            ak[r] += __shfl_xor_sync(0xffffffffu, ak[r], off);
        }
    }
    if (lane == 0) {
#pragma unroll
        for (int r = 0; r < RELS; ++r) {
            g_sq[r * n + gw] = aq[r];
            g_sk[r * n + gw] = ak[r];
        }
    }
}

// ---------------- fused: compute alpha + scatter into CSR slots ----------------
__global__ void k_fillalpha(const int* __restrict__ src, const int* __restrict__ dst,
                            const int* __restrict__ etype, const float* __restrict__ attr,
                            int n, int e_cnt) {
    int e = blockIdx.x * blockDim.x + threadIdx.x;
    if (e >= e_cnt) return;
    int s = src[e], d = dst[e], r = etype[e];
    float a = g_sq[r * n + d] + g_sk[r * n + s] + g_cattr * attr[e];
    a = (a > 0.f) ? a : 0.2f * a;
    int pos = atomicAdd(&g_cursor[d], 1);
    g_alphac[pos] = a;
    g_pack[pos] = (unsigned)s | ((unsigned)r << 28);
}

// ---------------- per-node softmax + aggregate raw x into g_agg; reset cursor ----------------
__global__ void k_agg(const float* __restrict__ xin, int n) {
    int gw = (blockIdx.x * blockDim.x + threadIdx.x) >> 5;
    int lane = threadIdx.x & 31;
    if (gw >= n) return;
    int beg = g_indptr[gw], end = g_indptr[gw + 1];

    float m = -CUDART_INF_F;
    for (int j = beg + lane; j < end; j += 32) m = fmaxf(m, g_alphac[j]);
#pragma unroll
    for (int off = 16; off; off >>= 1) m = fmaxf(m, __shfl_xor_sync(0xffffffffu, m, off));

    float s = 0.f;
    for (int j = beg + lane; j < end; j += 32) s += __expf(g_alphac[j] - m);
#pragma unroll
    for (int off = 16; off; off >>= 1) s += __shfl_xor_sync(0xffffffffu, s, off);
    float inv = 1.f / (s + 1e-16f);

    float4 a0 = make_float4(0.f, 0.f, 0.f, 0.f);
    float4 a1 = a0, a2 = a0;
    for (int j = beg; j < end; ++j) {
        float co = __expf(g_alphac[j] - m) * inv;
        unsigned p = g_pack[j];
        unsigned sv = p & 0x0FFFFFFFu;
        unsigned r = p >> 28;
        float4 v = ((const float4*)(xin + (size_t)sv * C))[lane];
        if (r == 0) {
            a0.x = fmaf(co, v.x, a0.x); a0.y = fmaf(co, v.y, a0.y);
            a0.z = fmaf(co, v.z, a0.z); a0.w = fmaf(co, v.w, a0.w);
        } else if (r == 1) {
            a1.x = fmaf(co, v.x, a1.x); a1.y = fmaf(co, v.y, a1.y);
            a1.z = fmaf(co, v.z, a1.z); a1.w = fmaf(co, v.w, a1.w);
        } else {
            a2.x = fmaf(co, v.x, a2.x); a2.y = fmaf(co, v.y, a2.y);
            a2.z = fmaf(co, v.z, a2.z); a2.w = fmaf(co, v.w, a2.w);
        }
    }
    float* ob = g_agg + (size_t)gw * KS;
    ((float4*)(ob))[lane]       = a0;
    ((float4*)(ob + C))[lane]   = a1;
    ((float4*)(ob + 2 * C))[lane] = a2;
    if (lane == 0) g_cursor[gw] = beg;   // reset for next layer's fill
}

// ---------------- stacked HMMA bf16 3-term GEMM: out = agg @ Wstack + bias (opt relu) ----------------
// CTA: 256 thr (8 warps), tile M=128 x N=128, K=384 in 6 chunks of 64. 2 CTAs/SM.
#define APADB 72
#define GEMM_SMEM (4 * 128 * APADB * 2)

__global__ __launch_bounds__(256, 2) void k_gemm_st(const float* __restrict__ A,
                                                    const float* __restrict__ bias,
                                                    float* __restrict__ out,
                                                    int relu, int n) {
    extern __shared__ __nv_bfloat16 smb[];
    __nv_bfloat16* Ah = smb;
    __nv_bfloat16* Al = Ah + 128 * APADB;
    __nv_bfloat16* Bh = Al + 128 * APADB;
    __nv_bfloat16* Bl = Bh + 128 * APADB;

    int m0 = blockIdx.x * 128;
    int tid = threadIdx.x;
    int lane = tid & 31;
    int wid = tid >> 5;
    int wm = wid & 1;
    int wn = wid >> 1;

    uint32_t aAh = smem_u32(Ah), aAl = smem_u32(Al);
    uint32_t aBh = smem_u32(Bh), aBl = smem_u32(Bl);

    int lrow = (lane & 7) + ((lane >> 3) & 1) * 8;
    int lkoff = (lane >> 4) * 8;
    uint32_t baseA = (uint32_t)((wm * 64 + lrow) * APADB + lkoff) * 2;
    uint32_t baseB = (uint32_t)((wn * 32 + lrow) * APADB + lkoff) * 2;

    float acc[4][4][4];
#pragma unroll
    for (int a = 0; a < 4; ++a)
#pragma unroll
        for (int b = 0; b < 4; ++b)
#pragma unroll
            for (int cc = 0; cc < 4; ++cc) acc[a][b][cc] = 0.f;

#pragma unroll 1
    for (int kc = 0; kc < KS; kc += 64) {
        // A: 128 rows x 64 k fp32 -> split bf16
        {
            int k4 = (tid & 15) * 4;
            int rb = tid >> 4;
#pragma unroll
            for (int it = 0; it < 8; ++it) {
                int row = rb + it * 16;
                float4 v = make_float4(0.f, 0.f, 0.f, 0.f);
                if (m0 + row < n)
                    v = *(const float4*)(A + (size_t)(m0 + row) * KS + kc + k4);
                __nv_bfloat16 hx = __float2bfloat16(v.x), hy = __float2bfloat16(v.y);
                __nv_bfloat16 hz = __float2bfloat16(v.z), hw = __float2bfloat16(v.w);
                *(__nv_bfloat162*)(Ah + row * APADB + k4)     = __nv_bfloat162(hx, hy);
                *(__nv_bfloat162*)(Ah + row * APADB + k4 + 2) = __nv_bfloat162(hz, hw);
                *(__nv_bfloat162*)(Al + row * APADB + k4) =
                    __nv_bfloat162(__float2bfloat16(v.x - __bfloat162float(hx)),
                                   __float2bfloat16(v.y - __bfloat162float(hy)));
                *(__nv_bfloat162*)(Al + row * APADB + k4 + 2) =
                    __nv_bfloat162(__float2bfloat16(v.z - __bfloat162float(hz)),
                                   __float2bfloat16(v.w - __bfloat162float(hw)));
            }
        }
        // B: 128 nout rows x 64 k (pre-split bf16 stacked)
        {
            int k4 = (tid & 15) * 4;
            int nb = tid >> 4;
#pragma unroll
            for (int it = 0; it < 8; ++it) {
                int nn = nb + it * 16;
                uint2 vh = *(const uint2*)(g_wts_hi + (size_t)nn * KS + kc + k4);
                uint2 vl = *(const uint2*)(g_wts_lo + (size_t)nn * KS + kc + k4);
                *(uint2*)(Bh + nn * APADB + k4) = vh;
                *(uint2*)(Bl + nn * APADB + k4) = vl;
            }
        }
        __syncthreads();

#pragma unroll
        for (int ks = 0; ks < 4; ++ks) {
            uint32_t koff = (uint32_t)(ks * 16) * 2;
            uint32_t ah[4][4], al[4][4], bh[4][2], bl[4][2];
#pragma unroll
            for (int mt = 0; mt < 4; ++mt) {
                ldsm_x4(ah[mt], aAh + baseA + koff + (uint32_t)(mt * 16 * APADB * 2));
                ldsm_x4(al[mt], aAl + baseA + koff + (uint32_t)(mt * 16 * APADB * 2));
            }
#pragma unroll
            for (int p = 0; p < 2; ++p) {
                uint32_t t4[4];
                ldsm_x4(t4, aBh + baseB + koff + (uint32_t)(p * 16 * APADB * 2));
                bh[2 * p][0] = t4[0]; bh[2 * p + 1][0] = t4[1];
                bh[2 * p][1] = t4[2]; bh[2 * p + 1][1] = t4[3];
                ldsm_x4(t4, aBl + baseB + koff + (uint32_t)(p * 16 * APADB * 2));
                bl[2 * p][0] = t4[0]; bl[2 * p + 1][0] = t4[1];
                bl[2 * p][1] = t4[2]; bl[2 * p + 1][1] = t4[3];
            }
#pragma unroll
            for (int mt = 0; mt < 4; ++mt)
#pragma unroll
                for (int nt = 0; nt < 4; ++nt) mma_bf16(acc[mt][nt], ah[mt], bh[nt]);
#pragma unroll
            for (int mt = 0; mt < 4; ++mt)
#pragma unroll
                for (int nt = 0; nt < 4; ++nt) mma_bf16(acc[mt][nt], ah[mt], bl[nt]);
#pragma unroll
            for (int mt = 0; mt < 4; ++mt)
#pragma unroll
                for (int nt = 0; nt < 4; ++nt) mma_bf16(acc[mt][nt], al[mt], bh[nt]);
        }
        __syncthreads();
    }

    // ---- epilogue: + bias, optional relu ----
    float bx[4][2];
#pragma unroll
    for (int nt = 0; nt < 4; ++nt) {
        int col = wn * 32 + nt * 8 + 2 * (lane & 3);
        bx[nt][0] = bias[col];
        bx[nt][1] = bias[col + 1];
    }
#pragma unroll
    for (int mt = 0; mt < 4; ++mt) {
        int row0 = m0 + wm * 64 + mt * 16 + (lane >> 2);
        int row1 = row0 + 8;
#pragma unroll
        for (int nt = 0; nt < 4; ++nt) {
            int col = wn * 32 + nt * 8 + 2 * (lane & 3);
            float2 o0 = make_float2(acc[mt][nt][0] + bx[nt][0], acc[mt][nt][1] + bx[nt][1]);
            float2 o1 = make_float2(acc[mt][nt][2] + bx[nt][0], acc[mt][nt][3] + bx[nt][1]);
            if (relu) {
                o0.x = fmaxf(o0.x, 0.f); o0.y = fmaxf(o0.y, 0.f);
                o1.x = fmaxf(o1.x, 0.f); o1.y = fmaxf(o1.y, 0.f);
            }
            if (row0 < n) *(float2*)(out + (size_t)row0 * C + col) = o0;
            if (row1 < n) *(float2*)(out + (size_t)row1 * C + col) = o1;
        }
    }
}

// ---------------- driver ----------------
extern "C" void kernel_launch(void* const* d_in, const int* in_sizes, int n_in,
                              void* d_out, int out_size) {
    const float* x    = (const float*)d_in[0];
    const int*   ei   = (const int*)d_in[1];
    const int*   et   = (const int*)d_in[2];
    const float* attr = (const float*)d_in[3];
    const float *w1 = (const float*)d_in[4],  *q1 = (const float*)d_in[5],
                *k1 = (const float*)d_in[6],  *le1 = (const float*)d_in[7],
                *e1 = (const float*)d_in[8],  *b1 = (const float*)d_in[9];
    const float *w2 = (const float*)d_in[10], *q2 = (const float*)d_in[11],
                *k2 = (const float*)d_in[12], *le2 = (const float*)d_in[13],
                *e2 = (const float*)d_in[14], *b2 = (const float*)d_in[15];

    int n = in_sizes[0] / C;
    int e_cnt = in_sizes[2];
    const int* src = ei;
    const int* dst = ei + e_cnt;

    float* h = nullptr;
    cudaGetSymbolAddress((void**)&h, g_h);
    float* agg = nullptr;
    cudaGetSymbolAddress((void**)&agg, g_agg);

    static bool attr_set = false;
    if (!attr_set) {
        cudaFuncSetAttribute(k_gemm_st, cudaFuncAttributeMaxDynamicSharedMemorySize, GEMM_SMEM);
        attr_set = true;
    }

    int nblk = (n + 1023) / 1024;
    int prep_grid = 2 * RELS + (RELS * C + 1 + 7) / 8;
    int gemm_grid = (n + 127) / 128;

    // CSR build (3 kernels; deg starts zeroed, re-zeroed by scanC)
    k_count<<<(e_cnt + 255) / 256, 256>>>(dst, e_cnt);
    k_scanA<<<nblk, 1024>>>(n);
    k_scanC<<<nblk, 1024>>>(n, nblk);

    // layer 1
    k_prepall<<<prep_grid, 256>>>(w1, q1, k1, le1, e1);
    k_sqk<<<(n + 7) / 8, 256>>>(x, n);
    k_fillalpha<<<(e_cnt + 255) / 256, 256>>>(src, dst, et, attr, n, e_cnt);
    k_agg<<<(n + 7) / 8, 256>>>(x, n);
    k_gemm_st<<<gemm_grid, 256, GEMM_SMEM>>>(agg, b1, h, 1, n);

    // layer 2
    k_prepall<<<prep_grid, 256>>>(w2, q2, k2, le2, e2);
    k_sqk<<<(n + 7) / 8, 256>>>(h, n);
    k_fillalpha<<<(e_cnt + 255) / 256, 256>>>(src, dst, et, attr, n, e_cnt);
    k_agg<<<(n + 7) / 8, 256>>>(h, n);
    k_gemm_st<<<gemm_grid, 256, GEMM_SMEM>>>(agg, b2, (float*)d_out, 0, n);
}

// round 10
// speedup vs baseline: 1.9021x; 1.0332x over previous
#include <cuda_runtime.h>
#include <cuda_bf16.h>
#include <math_constants.h>
#include <cstdint>

#define MAXN 50000
#define MAXE 500000
#define C    128
#define RELS 3
#define KS   (RELS * C)   // 384 stacked K

// ---------------- scratch (static device memory; no allocation) ----------------
__device__ __align__(16) __nv_bfloat16 g_agg_hi[(size_t)MAXN * KS];  // aggregated x, bf16 hi
__device__ __align__(16) __nv_bfloat16 g_agg_lo[(size_t)MAXN * KS];  // aggregated x, bf16 lo
__device__ __align__(16) float g_h[(size_t)MAXN * C];      // layer-1 output
__device__ float g_alphac[MAXE];                            // alpha in CSR order
__device__ unsigned g_pack[MAXE];                           // (r<<28)|src in CSR order
__device__ float g_sq[RELS * MAXN];
__device__ float g_sk[RELS * MAXN];
__device__ __align__(16) float g_wq[RELS * C];
__device__ __align__(16) float g_wk[RELS * C];
__device__ float g_cattr;
__device__ __align__(16) __nv_bfloat16 g_wts_hi[C * KS];   // stacked W^T hi: [nout][r*128+kin]
__device__ __align__(16) __nv_bfloat16 g_wts_lo[C * KS];
__device__ int g_deg[MAXN];          // zero-init; re-zeroed by k_scanC each run
__device__ int g_incl[MAXN];
__device__ int g_indptr[MAXN + 1];
__device__ int g_cursor[MAXN];
__device__ int g_bsum[64];

__device__ __forceinline__ uint32_t smem_u32(const void* p) {
    uint32_t a;
    asm("{ .reg .u64 t; cvta.to.shared.u64 t, %1; cvt.u32.u64 %0, t; }" : "=r"(a) : "l"(p));
    return a;
}
__device__ __forceinline__ void mma_bf16(float* c, const uint32_t* a, const uint32_t* b) {
    asm volatile(
        "mma.sync.aligned.m16n8k16.row.col.f32.bf16.bf16.f32 "
        "{%0,%1,%2,%3}, {%4,%5,%6,%7}, {%8,%9}, {%0,%1,%2,%3};"
        : "+f"(c[0]), "+f"(c[1]), "+f"(c[2]), "+f"(c[3])
        : "r"(a[0]), "r"(a[1]), "r"(a[2]), "r"(a[3]), "r"(b[0]), "r"(b[1]));
}
__device__ __forceinline__ void ldsm_x4(uint32_t* r, uint32_t addr) {
    asm volatile("ldmatrix.sync.aligned.m8n8.x4.shared.b16 {%0,%1,%2,%3}, [%4];"
                 : "=r"(r[0]), "=r"(r[1]), "=r"(r[2]), "=r"(r[3]) : "r"(addr));
}
// split a float4 into bf16 hi/lo pairs, store 8 bytes to each dst
__device__ __forceinline__ void store_split(__nv_bfloat16* hp, __nv_bfloat16* lp, float4 a) {
    __nv_bfloat16 h0 = __float2bfloat16(a.x), h1 = __float2bfloat16(a.y);
    __nv_bfloat16 h2 = __float2bfloat16(a.z), h3 = __float2bfloat16(a.w);
    __nv_bfloat162 hh0(h0, h1), hh1(h2, h3);
    __nv_bfloat162 ll0(__float2bfloat16(a.x - __bfloat162float(h0)),
                       __float2bfloat16(a.y - __bfloat162float(h1)));
    __nv_bfloat162 ll1(__float2bfloat16(a.z - __bfloat162float(h2)),
                       __float2bfloat16(a.w - __bfloat162float(h3)));
    ((__nv_bfloat162*)hp)[0] = hh0; ((__nv_bfloat162*)hp)[1] = hh1;
    ((__nv_bfloat162*)lp)[0] = ll0; ((__nv_bfloat162*)lp)[1] = ll1;
}

// ---------------- CSR build ----------------
__global__ void k_count(const int* __restrict__ dst, int e_cnt) {
    int e = blockIdx.x * blockDim.x + threadIdx.x;
    if (e < e_cnt) atomicAdd(&g_deg[dst[e]], 1);
}
__global__ void k_scanA(int n) {
    __shared__ int sh[2][1024];
    int tid = threadIdx.x;
    int i = blockIdx.x * 1024 + tid;
    int v = (i < n) ? g_deg[i] : 0;
    sh[0][tid] = v;
    __syncthreads();
    int pb = 0;
#pragma unroll
    for (int off = 1; off < 1024; off <<= 1) {
        int nb = pb ^ 1;
        int val = sh[pb][tid];
        if (tid >= off) val += sh[pb][tid - off];
        sh[nb][tid] = val;
        pb = nb;
        __syncthreads();
    }
    int incl = sh[pb][tid];
    if (i < n) g_incl[i] = incl;
    if (tid == 1023) g_bsum[blockIdx.x] = incl;
}
__global__ void k_scanC(int n, int nblk) {
    __shared__ int sb[64];
    int tid = threadIdx.x;
    int bid = blockIdx.x;
    if (tid < 64) sb[tid] = (tid < nblk) ? g_bsum[tid] : 0;
    __syncthreads();
#pragma unroll
    for (int off = 1; off < 64; off <<= 1) {
        int add = (tid < 64 && tid >= off) ? sb[tid - off] : 0;
        __syncthreads();
        if (tid < 64) sb[tid] += add;
        __syncthreads();
    }
    int base = (bid == 0) ? 0 : sb[bid - 1];
    int i = bid * 1024 + tid;
    if (i < n) {
        int total = g_incl[i] + base;
        g_indptr[i + 1] = total;
        g_cursor[i] = total - g_deg[i];
        g_deg[i] = 0;
        if (i == 0) g_indptr[0] = 0;
    }
}

// ---------------- per-layer precompute (tiled W transpose-split + wq/wk/cattr) ----------------
__global__ void k_prepall(const float* __restrict__ w, const float* __restrict__ q,
                          const float* __restrict__ kk, const float* __restrict__ le,
                          const float* __restrict__ ee) {
    if (blockIdx.x < 2 * RELS) {
        __shared__ float tile[64][129];
        int r = blockIdx.x >> 1;
        int kt = (blockIdx.x & 1) * 64;
        const float* Wr = w + (size_t)r * C * C;
        int tid = threadIdx.x;
#pragma unroll
        for (int it = 0; it < 8; ++it) {
            int idx = tid + it * 256;
            int kkr = idx >> 5;
            int nn4 = (idx & 31) * 4;
            float4 v = *(const float4*)(Wr + (size_t)(kt + kkr) * C + nn4);
            tile[kkr][nn4] = v.x; tile[kkr][nn4 + 1] = v.y;
            tile[kkr][nn4 + 2] = v.z; tile[kkr][nn4 + 3] = v.w;
        }
        __syncthreads();
        int lane = tid & 31, wid = tid >> 5;
        for (int nn = wid; nn < C; nn += 8) {
            float v0 = tile[2 * lane][nn];
            float v1 = tile[2 * lane + 1][nn];
            __nv_bfloat16 h0 = __float2bfloat16(v0), h1 = __float2bfloat16(v1);
            __nv_bfloat162 hh(h0, h1);
            __nv_bfloat162 ll(__float2bfloat16(v0 - __bfloat162float(h0)),
                              __float2bfloat16(v1 - __bfloat162float(h1)));
            size_t off = (size_t)nn * KS + r * C + kt + 2 * lane;
            *(__nv_bfloat162*)(g_wts_hi + off) = hh;
            *(__nv_bfloat162*)(g_wts_lo + off) = ll;
        }
        return;
    }
    int gw = (blockIdx.x - 2 * RELS) * 8 + (threadIdx.x >> 5);
    int lane = threadIdx.x & 31;
    if (gw < RELS * C) {
        const float4* row = (const float4*)(w + (size_t)gw * C);
        float4 wv = row[lane];
        float4 qv = ((const float4*)q)[lane];
        float4 kv = ((const float4*)kk)[lane];
        float aq = wv.x * qv.x + wv.y * qv.y + wv.z * qv.z + wv.w * qv.w;
        float ak = wv.x * kv.x + wv.y * kv.y + wv.z * kv.z + wv.w * kv.w;
#pragma unroll
        for (int off = 16; off; off >>= 1) {
            aq += __shfl_xor_sync(0xffffffffu, aq, off);
            ak += __shfl_xor_sync(0xffffffffu, ak, off);
        }
        if (lane == 0) { g_wq[gw] = aq; g_wk[gw] = ak; }
    } else if (gw == RELS * C) {
        float p = 0.f;
        for (int o = lane; o < C; o += 32) p += le[o] * ee[o];
#pragma unroll
        for (int off = 16; off; off >>= 1) p += __shfl_xor_sync(0xffffffffu, p, off);
        if (lane == 0) g_cattr = p;
    }
}

// ---------------- per-node attention scalars ----------------
__global__ void k_sqk(const float* __restrict__ x, int n) {
    int gw = (blockIdx.x * blockDim.x + threadIdx.x) >> 5;
    int lane = threadIdx.x & 31;
    if (gw >= n) return;
    float4 xv = ((const float4*)x)[(size_t)gw * 32 + lane];
    float aq[RELS], ak[RELS];
#pragma unroll
    for (int r = 0; r < RELS; ++r) {
        float4 wqv = ((const float4*)g_wq)[r * 32 + lane];
        float4 wkv = ((const float4*)g_wk)[r * 32 + lane];
        aq[r] = xv.x * wqv.x + xv.y * wqv.y + xv.z * wqv.z + xv.w * wqv.w;
        ak[r] = xv.x * wkv.x + xv.y * wkv.y + xv.z * wkv.z + xv.w * wkv.w;
    }
#pragma unroll
    for (int off = 16; off; off >>= 1) {
#pragma unroll
        for (int r = 0; r < RELS; ++r) {
            aq[r] += __shfl_xor_sync(0xffffffffu, aq[r], off);
            ak[r] += __shfl_xor_sync(0xffffffffu, ak[r], off);
        }
    }
    if (lane == 0) {
#pragma unroll
        for (int r = 0; r < RELS; ++r) {
            g_sq[r * n + gw] = aq[r];
            g_sk[r * n + gw] = ak[r];
        }
    }
}

// ---------------- fused: compute alpha + scatter into CSR slots ----------------
__global__ void k_fillalpha(const int* __restrict__ src, const int* __restrict__ dst,
                            const int* __restrict__ etype, const float* __restrict__ attr,
                            int n, int e_cnt) {
    int e = blockIdx.x * blockDim.x + threadIdx.x;
    if (e >= e_cnt) return;
    int s = src[e], d = dst[e], r = etype[e];
    float a = g_sq[r * n + d] + g_sk[r * n + s] + g_cattr * attr[e];
    a = (a > 0.f) ? a : 0.2f * a;
    int pos = atomicAdd(&g_cursor[d], 1);
    g_alphac[pos] = a;
    g_pack[pos] = (unsigned)s | ((unsigned)r << 28);
}

// ---------------- per-node softmax + aggregate raw x -> bf16-split g_agg; reset cursor ----------------
#define ACCUM(rr, co, v)                                                     \
    do {                                                                     \
        if ((rr) == 0) {                                                     \
            a0.x = fmaf(co, (v).x, a0.x); a0.y = fmaf(co, (v).y, a0.y);      \
            a0.z = fmaf(co, (v).z, a0.z); a0.w = fmaf(co, (v).w, a0.w);      \
        } else if ((rr) == 1) {                                              \
            a1.x = fmaf(co, (v).x, a1.x); a1.y = fmaf(co, (v).y, a1.y);      \
            a1.z = fmaf(co, (v).z, a1.z); a1.w = fmaf(co, (v).w, a1.w);      \
        } else {                                                             \
            a2.x = fmaf(co, (v).x, a2.x); a2.y = fmaf(co, (v).y, a2.y);      \
            a2.z = fmaf(co, (v).z, a2.z); a2.w = fmaf(co, (v).w, a2.w);      \
        }                                                                    \
    } while (0)

__global__ void k_agg(const float* __restrict__ xin, int n) {
    int gw = (blockIdx.x * blockDim.x + threadIdx.x) >> 5;
    int lane = threadIdx.x & 31;
    if (gw >= n) return;
    int beg = g_indptr[gw], end = g_indptr[gw + 1];

    float m = -CUDART_INF_F;
    for (int j = beg + lane; j < end; j += 32) m = fmaxf(m, g_alphac[j]);
#pragma unroll
    for (int off = 16; off; off >>= 1) m = fmaxf(m, __shfl_xor_sync(0xffffffffu, m, off));

    float s = 0.f;
    for (int j = beg + lane; j < end; j += 32) s += __expf(g_alphac[j] - m);
#pragma unroll
    for (int off = 16; off; off >>= 1) s += __shfl_xor_sync(0xffffffffu, s, off);
    float inv = 1.f / (s + 1e-16f);

    float4 a0 = make_float4(0.f, 0.f, 0.f, 0.f);
    float4 a1 = a0, a2 = a0;
    int j = beg;
    for (; j + 1 < end; j += 2) {
        float al0 = g_alphac[j], al1 = g_alphac[j + 1];
        unsigned p0 = g_pack[j], p1 = g_pack[j + 1];
        float4 v0 = ((const float4*)(xin + (size_t)(p0 & 0x0FFFFFFFu) * C))[lane];
        float4 v1 = ((const float4*)(xin + (size_t)(p1 & 0x0FFFFFFFu) * C))[lane];
        float c0 = __expf(al0 - m) * inv;
        float c1 = __expf(al1 - m) * inv;
        unsigned r0 = p0 >> 28, r1 = p1 >> 28;
        ACCUM(r0, c0, v0);
        ACCUM(r1, c1, v1);
    }
    if (j < end) {
        float al0 = g_alphac[j];
        unsigned p0 = g_pack[j];
        float4 v0 = ((const float4*)(xin + (size_t)(p0 & 0x0FFFFFFFu) * C))[lane];
        float c0 = __expf(al0 - m) * inv;
        unsigned r0 = p0 >> 28;
        ACCUM(r0, c0, v0);
    }
    size_t ob = (size_t)gw * KS + (size_t)lane * 4;
    store_split(g_agg_hi + ob,         g_agg_lo + ob,         a0);
    store_split(g_agg_hi + ob + C,     g_agg_lo + ob + C,     a1);
    store_split(g_agg_hi + ob + 2 * C, g_agg_lo + ob + 2 * C, a2);
    if (lane == 0) g_cursor[gw] = beg;   // reset for next layer's fill
}

// ---------------- stacked HMMA bf16 3-term GEMM: out = agg @ Wstack + bias (opt relu) ----------------
// A and B both pre-split bf16 in global -> chunk loads are pure uint4 copies.
#define APADB 72
#define GEMM_SMEM (4 * 128 * APADB * 2)

__global__ __launch_bounds__(256, 2) void k_gemm_st(const float* __restrict__ bias,
                                                    float* __restrict__ out,
                                                    int relu, int n) {
    extern __shared__ __nv_bfloat16 smb[];
    __nv_bfloat16* Ah = smb;
    __nv_bfloat16* Al = Ah + 128 * APADB;
    __nv_bfloat16* Bh = Al + 128 * APADB;
    __nv_bfloat16* Bl = Bh + 128 * APADB;

    int m0 = blockIdx.x * 128;
    int tid = threadIdx.x;
    int lane = tid & 31;
    int wid = tid >> 5;
    int wm = wid & 1;
    int wn = wid >> 1;

    uint32_t aAh = smem_u32(Ah), aAl = smem_u32(Al);
    uint32_t aBh = smem_u32(Bh), aBl = smem_u32(Bl);

    int lrow = (lane & 7) + ((lane >> 3) & 1) * 8;
    int lkoff = (lane >> 4) * 8;
    uint32_t baseA = (uint32_t)((wm * 64 + lrow) * APADB + lkoff) * 2;
    uint32_t baseB = (uint32_t)((wn * 32 + lrow) * APADB + lkoff) * 2;

    float acc[4][4][4];
#pragma unroll
    for (int a = 0; a < 4; ++a)
#pragma unroll
        for (int b = 0; b < 4; ++b)
#pragma unroll
            for (int cc = 0; cc < 4; ++cc) acc[a][b][cc] = 0.f;

    const uint4 zero4 = make_uint4(0u, 0u, 0u, 0u);
    int u4 = tid & 7;          // which 16B group within a 64-k (128B) chunk row
    int rb = tid >> 3;         // 0..31

#pragma unroll 1
    for (int kc = 0; kc < KS; kc += 64) {
        // A: 128 rows x 64 k, bf16 hi/lo copies
#pragma unroll
        for (int it = 0; it < 4; ++it) {
            int row = rb + it * 32;
            uint4 vh = zero4, vl = zero4;
            if (m0 + row < n) {
                size_t goff = (size_t)(m0 + row) * KS + kc + u4 * 8;
                vh = *(const uint4*)(g_agg_hi + goff);
                vl = *(const uint4*)(g_agg_lo + goff);
            }
            *(uint4*)(Ah + row * APADB + u4 * 8) = vh;
            *(uint4*)(Al + row * APADB + u4 * 8) = vl;
        }
        // B: 128 nout rows x 64 k, bf16 hi/lo copies
#pragma unroll
        for (int it = 0; it < 4; ++it) {
            int nn = rb + it * 32;
            size_t goff = (size_t)nn * KS + kc + u4 * 8;
            *(uint4*)(Bh + nn * APADB + u4 * 8) = *(const uint4*)(g_wts_hi + goff);
            *(uint4*)(Bl + nn * APADB + u4 * 8) = *(const uint4*)(g_wts_lo + goff);
        }
        __syncthreads();

#pragma unroll
        for (int ks = 0; ks < 4; ++ks) {
            uint32_t koff = (uint32_t)(ks * 16) * 2;
            uint32_t ah[4][4], al[4][4], bh[4][2], bl[4][2];
#pragma unroll
            for (int mt = 0; mt < 4; ++mt) {
                ldsm_x4(ah[mt], aAh + baseA + koff + (uint32_t)(mt * 16 * APADB * 2));
                ldsm_x4(al[mt], aAl + baseA + koff + (uint32_t)(mt * 16 * APADB * 2));
            }
#pragma unroll
            for (int p = 0; p < 2; ++p) {
                uint32_t t4[4];
                ldsm_x4(t4, aBh + baseB + koff + (uint32_t)(p * 16 * APADB * 2));
                bh[2 * p][0] = t4[0]; bh[2 * p + 1][0] = t4[1];
                bh[2 * p][1] = t4[2]; bh[2 * p + 1][1] = t4[3];
                ldsm_x4(t4, aBl + baseB + koff + (uint32_t)(p * 16 * APADB * 2));
                bl[2 * p][0] = t4[0]; bl[2 * p + 1][0] = t4[1];
                bl[2 * p][1] = t4[2]; bl[2 * p + 1][1] = t4[3];
            }
#pragma unroll
            for (int mt = 0; mt < 4; ++mt)
#pragma unroll
                for (int nt = 0; nt < 4; ++nt) mma_bf16(acc[mt][nt], ah[mt], bh[nt]);
#pragma unroll
            for (int mt = 0; mt < 4; ++mt)
#pragma unroll
                for (int nt = 0; nt < 4; ++nt) mma_bf16(acc[mt][nt], ah[mt], bl[nt]);
#pragma unroll
            for (int mt = 0; mt < 4; ++mt)
#pragma unroll
                for (int nt = 0; nt < 4; ++nt) mma_bf16(acc[mt][nt], al[mt], bh[nt]);
        }
        __syncthreads();
    }

    // ---- epilogue: + bias, optional relu ----
    float bx[4][2];
#pragma unroll
    for (int nt = 0; nt < 4; ++nt) {
        int col = wn * 32 + nt * 8 + 2 * (lane & 3);
        bx[nt][0] = bias[col];
        bx[nt][1] = bias[col + 1];
    }
#pragma unroll
    for (int mt = 0; mt < 4; ++mt) {
        int row0 = m0 + wm * 64 + mt * 16 + (lane >> 2);
        int row1 = row0 + 8;
#pragma unroll
        for (int nt = 0; nt < 4; ++nt) {
            int col = wn * 32 + nt * 8 + 2 * (lane & 3);
            float2 o0 = make_float2(acc[mt][nt][0] + bx[nt][0], acc[mt][nt][1] + bx[nt][1]);
            float2 o1 = make_float2(acc[mt][nt][2] + bx[nt][0], acc[mt][nt][3] + bx[nt][1]);
            if (relu) {
                o0.x = fmaxf(o0.x, 0.f); o0.y = fmaxf(o0.y, 0.f);
                o1.x = fmaxf(o1.x, 0.f); o1.y = fmaxf(o1.y, 0.f);
            }
            if (row0 < n) *(float2*)(out + (size_t)row0 * C + col) = o0;
            if (row1 < n) *(float2*)(out + (size_t)row1 * C + col) = o1;
        }
    }
}

// ---------------- driver ----------------
extern "C" void kernel_launch(void* const* d_in, const int* in_sizes, int n_in,
                              void* d_out, int out_size) {
    const float* x    = (const float*)d_in[0];
    const int*   ei   = (const int*)d_in[1];
    const int*   et   = (const int*)d_in[2];
    const float* attr = (const float*)d_in[3];
    const float *w1 = (const float*)d_in[4],  *q1 = (const float*)d_in[5],
                *k1 = (const float*)d_in[6],  *le1 = (const float*)d_in[7],
                *e1 = (const float*)d_in[8],  *b1 = (const float*)d_in[9];
    const float *w2 = (const float*)d_in[10], *q2 = (const float*)d_in[11],
                *k2 = (const float*)d_in[12], *le2 = (const float*)d_in[13],
                *e2 = (const float*)d_in[14], *b2 = (const float*)d_in[15];

    int n = in_sizes[0] / C;
    int e_cnt = in_sizes[2];
    const int* src = ei;
    const int* dst = ei + e_cnt;

    float* h = nullptr;
    cudaGetSymbolAddress((void**)&h, g_h);

    static bool attr_set = false;
    if (!attr_set) {
        cudaFuncSetAttribute(k_gemm_st, cudaFuncAttributeMaxDynamicSharedMemorySize, GEMM_SMEM);
        attr_set = true;
    }

    int nblk = (n + 1023) / 1024;
    int prep_grid = 2 * RELS + (RELS * C + 1 + 7) / 8;
    int gemm_grid = (n + 127) / 128;

    // CSR build
    k_count<<<(e_cnt + 255) / 256, 256>>>(dst, e_cnt);
    k_scanA<<<nblk, 1024>>>(n);
    k_scanC<<<nblk, 1024>>>(n, nblk);

    // layer 1
    k_prepall<<<prep_grid, 256>>>(w1, q1, k1, le1, e1);
    k_sqk<<<(n + 7) / 8, 256>>>(x, n);
    k_fillalpha<<<(e_cnt + 255) / 256, 256>>>(src, dst, et, attr, n, e_cnt);
    k_agg<<<(n + 7) / 8, 256>>>(x, n);
    k_gemm_st<<<gemm_grid, 256, GEMM_SMEM>>>(b1, h, 1, n);

    // layer 2
    k_prepall<<<prep_grid, 256>>>(w2, q2, k2, le2, e2);
    k_sqk<<<(n + 7) / 8, 256>>>(h, n);
    k_fillalpha<<<(e_cnt + 255) / 256, 256>>>(src, dst, et, attr, n, e_cnt);
    k_agg<<<(n + 7) / 8, 256>>>(h, n);
    k_gemm_st<<<gemm_grid, 256, GEMM_SMEM>>>(b2, (float*)d_out, 0, n);
}